// round 13
// baseline (speedup 1.0000x reference)
#include <cuda_runtime.h>
#include <cuda_bf16.h>
#include <math.h>

// Problem constants
#define BB   4
#define SS   1024
#define DIN  256
#define VV   256
#define KDIM 64
#define HH   8
#define TT   4
#define BS   (BB*SS)          // 4096
#define NCH  32               // stat chunks per head
#define EPS  1e-3f
#define NTILE 16              // SS / 64 score tiles per row

// ---------------- scratch (device globals; no allocation allowed) -----------
__device__ float g_net[HH*BS*VV];
__device__ float g_q[HH*BS*KDIM];
__device__ float g_k[HH*BS*KDIM];
__device__ float g_v[HH*BS*VV];
__device__ float g_scores[(size_t)HH*BB*SS*SS];  // raw scaled scores, 134MB
__device__ float g_z[HH*BS*VV];
__device__ float g_part[HH*NCH*VV*2];
__device__ float g_smpart[HH*BB*SS*NTILE*2];     // per-tile (max, sumexp)
__device__ float2 g_ml[HH*BB*SS];                // per-row (max, 1/L)

// ---------------- TF32 helpers ----------------------------------------------
__device__ __forceinline__ unsigned f2tf(float f) {
    unsigned r;
    asm("cvt.rna.tf32.f32 %0, %1;" : "=r"(r) : "f"(f));
    return r;
}

__device__ __forceinline__ void split_tf32(float f, unsigned &hi, unsigned &lo) {
    hi = f2tf(f);
    lo = f2tf(f - __uint_as_float(hi));
}

__device__ __forceinline__ void mma_tf32(float c[4],
                                         const unsigned a[4],
                                         const unsigned b[2]) {
    asm volatile(
        "mma.sync.aligned.m16n8k8.row.col.f32.tf32.tf32.f32 "
        "{%0,%1,%2,%3}, {%4,%5,%6,%7}, {%8,%9}, {%0,%1,%2,%3};"
        : "+f"(c[0]), "+f"(c[1]), "+f"(c[2]), "+f"(c[3])
        : "r"(a[0]), "r"(a[1]), "r"(a[2]), "r"(a[3]), "r"(b[0]), "r"(b[1]));
}

// ---------------- 3xTF32 tensor-core GEMM core (R8-proven) -------------------
#define GBM 128
#define GBN 64
#define GBK 32
#define ASTR 36
#define BSTR_NN 72
#define BSTR_NT 36
#define A_TILE (GBM*ASTR)
#define B_TILE 2304
#define SMEM_U32 (2*A_TILE + 2*B_TILE)   // 13824 u32 = 55296 B

// EPI: 0 = plain C=alpha*acc (with rep)
//      1 = attnout fuse: y=R+acc, C=y, stats (h=z>>2, chunk=(z&3)*8+by)
//      2 = Wd fuse:      y=R+relu(acc), C=y, stats (h=z, chunk=by)
//      3 = scores: C=alpha*acc, plus per-row (max, sumexp) tile partials
// ASOFT: A-loader applies P = exp(a - M_row) * invL_row from ml[]
template<int NT, int EPI, int ASOFT>
__global__ void __launch_bounds__(256)
gemm_mma(const float* __restrict__ A, const float* __restrict__ B,
         float* __restrict__ C, const float* __restrict__ R,
         float* __restrict__ part,
         float* __restrict__ smpart, const float2* __restrict__ ml,
         int M, int N, int K,
         long long sA, long long sB, long long sC, long long sR,
         float alpha, int rep, long long repStride)
{
    A += (long long)blockIdx.z * sA;
    B += (long long)blockIdx.z * sB;
    C += (long long)blockIdx.z * sC;
    if (EPI == 1 || EPI == 2) R += (long long)blockIdx.z * sR;

    extern __shared__ unsigned smem[];
    unsigned* AsH = smem;
    unsigned* AsL = smem + A_TILE;
    unsigned* BsH = smem + 2*A_TILE;
    unsigned* BsL = smem + 2*A_TILE + B_TILE;

    const int t    = threadIdx.x;
    const int lane = t & 31;
    const int wid  = t >> 5;
    const int gid  = lane >> 2;
    const int tig  = lane & 3;
    const int wm   = (wid & 3) * 32;
    const int wn   = (wid >> 2) * 32;
    const int m0 = blockIdx.y * GBM, n0 = blockIdx.x * GBN;

    // ASOFT: per-thread row softmax params (4 fixed A rows per thread)
    float mlm[4], mli[4];
    if (ASOFT) {
        const float2* mlb = ml + (size_t)blockIdx.z * SS + m0;
        #pragma unroll
        for (int i = 0; i < 4; i++) {
            float2 p = mlb[(t >> 3) + i * 32];
            mlm[i] = p.x; mli[i] = p.y;
        }
    }

    float acc[2][4][4] = {};

    for (int k0 = 0; k0 < K; k0 += GBK) {
        float4 ar[4];
        #pragma unroll
        for (int i = 0; i < 4; i++) {
            int idx = t + i * 256;
            int r = idx >> 3, c4 = (idx & 7) << 2;
            ar[i] = *(const float4*)&A[(size_t)(m0 + r) * K + k0 + c4];
            if (ASOFT) {
                ar[i].x = __expf(ar[i].x - mlm[i]) * mli[i];
                ar[i].y = __expf(ar[i].y - mlm[i]) * mli[i];
                ar[i].z = __expf(ar[i].z - mlm[i]) * mli[i];
                ar[i].w = __expf(ar[i].w - mlm[i]) * mli[i];
            }
        }
        float4 br[2];
        #pragma unroll
        for (int i = 0; i < 2; i++) {
            int idx = t + i * 256;
            if (NT) {
                int r = idx >> 3, c4 = (idx & 7) << 2;
                br[i] = *(const float4*)&B[(size_t)(n0 + r) * K + k0 + c4];
            } else {
                int r = idx >> 4, c4 = (idx & 15) << 2;
                br[i] = *(const float4*)&B[(size_t)(k0 + r) * N + n0 + c4];
            }
        }
        __syncthreads();
        #pragma unroll
        for (int i = 0; i < 4; i++) {
            int idx = t + i * 256;
            int r = idx >> 3, c4 = (idx & 7) << 2;
            unsigned* ph = &AsH[r * ASTR + c4];
            unsigned* pl = &AsL[r * ASTR + c4];
            split_tf32(ar[i].x, ph[0], pl[0]);
            split_tf32(ar[i].y, ph[1], pl[1]);
            split_tf32(ar[i].z, ph[2], pl[2]);
            split_tf32(ar[i].w, ph[3], pl[3]);
        }
        #pragma unroll
        for (int i = 0; i < 2; i++) {
            int idx = t + i * 256;
            int off;
            if (NT) { int r = idx >> 3, c4 = (idx & 7) << 2;  off = r * BSTR_NT + c4; }
            else    { int r = idx >> 4, c4 = (idx & 15) << 2; off = r * BSTR_NN + c4; }
            unsigned* ph = &BsH[off];
            unsigned* pl = &BsL[off];
            split_tf32(br[i].x, ph[0], pl[0]);
            split_tf32(br[i].y, ph[1], pl[1]);
            split_tf32(br[i].z, ph[2], pl[2]);
            split_tf32(br[i].w, ph[3], pl[3]);
        }
        __syncthreads();

        #pragma unroll
        for (int ks = 0; ks < 4; ks++) {
            const int kk = ks * 8;
            unsigned aH[2][4], aL[2][4];
            #pragma unroll
            for (int i = 0; i < 2; i++) {
                const int mr = wm + i * 16;
                const int o0 = (mr + gid    ) * ASTR + kk + tig;
                const int o1 = (mr + gid + 8) * ASTR + kk + tig;
                aH[i][0] = AsH[o0];     aL[i][0] = AsL[o0];
                aH[i][1] = AsH[o1];     aL[i][1] = AsL[o1];
                aH[i][2] = AsH[o0 + 4]; aL[i][2] = AsL[o0 + 4];
                aH[i][3] = AsH[o1 + 4]; aL[i][3] = AsL[o1 + 4];
            }
            unsigned bH[4][2], bL[4][2];
            #pragma unroll
            for (int j = 0; j < 4; j++) {
                const int nc = wn + j * 8 + gid;
                int o0, o1;
                if (NT) { o0 = nc * BSTR_NT + kk + tig;  o1 = o0 + 4; }
                else    { o0 = (kk + tig) * BSTR_NN + nc; o1 = o0 + 4 * BSTR_NN; }
                bH[j][0] = BsH[o0]; bL[j][0] = BsL[o0];
                bH[j][1] = BsH[o1]; bL[j][1] = BsL[o1];
            }
            #pragma unroll
            for (int i = 0; i < 2; i++)
                #pragma unroll
                for (int j = 0; j < 4; j++) {
                    mma_tf32(acc[i][j], aL[i], bH[j]);
                    mma_tf32(acc[i][j], aH[i], bL[j]);
                    mma_tf32(acc[i][j], aH[i], bH[j]);
                }
        }
        __syncthreads();
    }

    if (EPI == 0 || EPI == 3) {
        // scale in place, write C
        #pragma unroll
        for (int i = 0; i < 2; i++)
            #pragma unroll
            for (int j = 0; j < 4; j++) {
                #pragma unroll
                for (int e = 0; e < 4; e++) acc[i][j][e] *= alpha;
                const int r0 = m0 + wm + i * 16 + gid;
                const int c0 = n0 + wn + j * 8 + tig * 2;
                float2 v01 = make_float2(acc[i][j][0], acc[i][j][1]);
                float2 v23 = make_float2(acc[i][j][2], acc[i][j][3]);
                for (int r = 0; r < rep; r++) {
                    *(float2*)&C[(size_t)r0 * N + c0 + (size_t)r * repStride] = v01;
                    *(float2*)&C[(size_t)(r0 + 8) * N + c0 + (size_t)r * repStride] = v23;
                }
            }
        if (EPI == 3) {
            // per-row (over this CTA's 64 cols) max & sumexp partials.
            // Thread rows: wm+gid+{0,8,16,24} (r = 0..3)
            float rmx[4] = {-INFINITY, -INFINITY, -INFINITY, -INFINITY};
            #pragma unroll
            for (int j = 0; j < 4; j++) {
                rmx[0] = fmaxf(rmx[0], fmaxf(acc[0][j][0], acc[0][j][1]));
                rmx[1] = fmaxf(rmx[1], fmaxf(acc[0][j][2], acc[0][j][3]));
                rmx[2] = fmaxf(rmx[2], fmaxf(acc[1][j][0], acc[1][j][1]));
                rmx[3] = fmaxf(rmx[3], fmaxf(acc[1][j][2], acc[1][j][3]));
            }
            #pragma unroll
            for (int r = 0; r < 4; r++) {
                rmx[r] = fmaxf(rmx[r], __shfl_xor_sync(0xffffffffu, rmx[r], 1));
                rmx[r] = fmaxf(rmx[r], __shfl_xor_sync(0xffffffffu, rmx[r], 2));
            }
            float* wr   = (float*)smem;        // [2][128] warp-col max
            float* Mrow = wr + 256;            // [128]
            float* ws   = Mrow + 128;          // [2][128] sumexp
            const int wc = wid >> 2;
            __syncthreads();
            if (tig == 0) {
                #pragma unroll
                for (int r = 0; r < 4; r++)
                    wr[wc * 128 + wm + gid + r * 8] = rmx[r];
            }
            __syncthreads();
            float Mr[4];
            #pragma unroll
            for (int r = 0; r < 4; r++)
                Mr[r] = fmaxf(wr[wm + gid + r * 8], wr[128 + wm + gid + r * 8]);
            float rs[4] = {};
            #pragma unroll
            for (int j = 0; j < 4; j++) {
                rs[0] += __expf(acc[0][j][0] - Mr[0]) + __expf(acc[0][j][1] - Mr[0]);
                rs[1] += __expf(acc[0][j][2] - Mr[1]) + __expf(acc[0][j][3] - Mr[1]);
                rs[2] += __expf(acc[1][j][0] - Mr[2]) + __expf(acc[1][j][1] - Mr[2]);
                rs[3] += __expf(acc[1][j][2] - Mr[3]) + __expf(acc[1][j][3] - Mr[3]);
            }
            #pragma unroll
            for (int r = 0; r < 4; r++) {
                rs[r] += __shfl_xor_sync(0xffffffffu, rs[r], 1);
                rs[r] += __shfl_xor_sync(0xffffffffu, rs[r], 2);
            }
            if (tig == 0) {
                #pragma unroll
                for (int r = 0; r < 4; r++) {
                    ws[wc * 128 + wm + gid + r * 8] = rs[r];
                    if (wc == 0) Mrow[wm + gid + r * 8] = Mr[r];
                }
            }
            __syncthreads();
            if (t < 128) {
                float Mf = Mrow[t];
                float Lf = ws[t] + ws[128 + t];
                size_t o = ((size_t)(blockIdx.z * SS + m0 + t) * NTILE + blockIdx.x) * 2;
                smpart[o + 0] = Mf;
                smpart[o + 1] = Lf;
            }
        }
    } else {
        // y = R + (relu?)(acc); C = y; per-block column stats -> part
        float colsum[8] = {}, colsq[8] = {};
        #pragma unroll
        for (int i = 0; i < 2; i++)
            #pragma unroll
            for (int j = 0; j < 4; j++) {
                const int r0 = m0 + wm + i * 16 + gid;
                const int c0 = n0 + wn + j * 8 + tig * 2;
                float2 a0 = *(const float2*)&R[(size_t)r0 * N + c0];
                float2 a1 = *(const float2*)&R[(size_t)(r0 + 8) * N + c0];
                float v0 = acc[i][j][0], v1 = acc[i][j][1];
                float v2 = acc[i][j][2], v3 = acc[i][j][3];
                if (EPI == 2) {
                    v0 = fmaxf(v0, 0.f); v1 = fmaxf(v1, 0.f);
                    v2 = fmaxf(v2, 0.f); v3 = fmaxf(v3, 0.f);
                }
                float y00 = a0.x + v0, y01 = a0.y + v1;
                float y10 = a1.x + v2, y11 = a1.y + v3;
                *(float2*)&C[(size_t)r0 * N + c0]       = make_float2(y00, y01);
                *(float2*)&C[(size_t)(r0 + 8) * N + c0] = make_float2(y10, y11);
                colsum[j*2+0] += y00 + y10;
                colsum[j*2+1] += y01 + y11;
                colsq [j*2+0] += y00*y00 + y10*y10;
                colsq [j*2+1] += y01*y01 + y11*y11;
            }
        #pragma unroll
        for (int c8 = 0; c8 < 8; c8++) {
            #pragma unroll
            for (int msk = 4; msk <= 16; msk <<= 1) {
                colsum[c8] += __shfl_xor_sync(0xffffffffu, colsum[c8], msk);
                colsq [c8] += __shfl_xor_sync(0xffffffffu, colsq [c8], msk);
            }
        }
        float* sred = (float*)smem;   // [4 m-warps][64 cols][2]
        __syncthreads();
        if (gid == 0) {
            #pragma unroll
            for (int j = 0; j < 4; j++)
                #pragma unroll
                for (int e = 0; e < 2; e++) {
                    int col = wn + j * 8 + tig * 2 + e;
                    int idx = ((wid & 3) * 64 + col) * 2;
                    sred[idx + 0] = colsum[j*2+e];
                    sred[idx + 1] = colsq [j*2+e];
                }
        }
        __syncthreads();
        if (t < 64) {
            float s = 0.f, q2 = 0.f;
            #pragma unroll
            for (int w = 0; w < 4; w++) {
                s  += sred[(w * 64 + t) * 2 + 0];
                q2 += sred[(w * 64 + t) * 2 + 1];
            }
            int hh, chunk;
            if (EPI == 1) { hh = blockIdx.z >> 2; chunk = (blockIdx.z & 3) * 8 + blockIdx.y; }
            else          { hh = blockIdx.z;      chunk = blockIdx.y; }
            size_t p = ((size_t)(hh * NCH + chunk) * VV + (n0 + t)) * 2;
            part[p + 0] = s;
            part[p + 1] = q2;
        }
    }
}

// ---------------- fused q/k/v projection (one launch) ------------------------
__global__ void __launch_bounds__(256)
gemm_qkv(const float* __restrict__ net,
         const float* __restrict__ Wq_t, const float* __restrict__ Wk_t,
         const float* __restrict__ Wv_t,
         float* __restrict__ q, float* __restrict__ k, float* __restrict__ v)
{
    const int h = blockIdx.z;
    const int bx = blockIdx.x;
    const float* A = net + (size_t)h * BS * VV;
    const float* B;
    float* C;
    int N, n0;
    if (bx == 0)      { B = Wq_t + (size_t)h * TT * VV * KDIM; C = q + (size_t)h * BS * KDIM; N = KDIM; n0 = 0; }
    else if (bx == 1) { B = Wk_t + (size_t)h * TT * VV * KDIM; C = k + (size_t)h * BS * KDIM; N = KDIM; n0 = 0; }
    else              { B = Wv_t + (size_t)h * TT * VV * VV;   C = v + (size_t)h * BS * VV;   N = VV;   n0 = (bx - 2) * GBN; }
    const int K = VV;

    extern __shared__ unsigned smem[];
    unsigned* AsH = smem;
    unsigned* AsL = smem + A_TILE;
    unsigned* BsH = smem + 2*A_TILE;
    unsigned* BsL = smem + 2*A_TILE + B_TILE;

    const int t    = threadIdx.x;
    const int lane = t & 31;
    const int wid  = t >> 5;
    const int gid  = lane >> 2;
    const int tig  = lane & 3;
    const int wm   = (wid & 3) * 32;
    const int wn   = (wid >> 2) * 32;
    const int m0 = blockIdx.y * GBM;

    float acc[2][4][4] = {};

    for (int k0 = 0; k0 < K; k0 += GBK) {
        float4 ar[4];
        #pragma unroll
        for (int i = 0; i < 4; i++) {
            int idx = t + i * 256;
            int r = idx >> 3, c4 = (idx & 7) << 2;
            ar[i] = *(const float4*)&A[(size_t)(m0 + r) * K + k0 + c4];
        }
        float4 br[2];
        #pragma unroll
        for (int i = 0; i < 2; i++) {
            int idx = t + i * 256;
            int r = idx >> 4, c4 = (idx & 15) << 2;
            br[i] = *(const float4*)&B[(size_t)(k0 + r) * N + n0 + c4];
        }
        __syncthreads();
        #pragma unroll
        for (int i = 0; i < 4; i++) {
            int idx = t + i * 256;
            int r = idx >> 3, c4 = (idx & 7) << 2;
            unsigned* ph = &AsH[r * ASTR + c4];
            unsigned* pl = &AsL[r * ASTR + c4];
            split_tf32(ar[i].x, ph[0], pl[0]);
            split_tf32(ar[i].y, ph[1], pl[1]);
            split_tf32(ar[i].z, ph[2], pl[2]);
            split_tf32(ar[i].w, ph[3], pl[3]);
        }
        #pragma unroll
        for (int i = 0; i < 2; i++) {
            int idx = t + i * 256;
            int r = idx >> 4, c4 = (idx & 15) << 2;
            int off = r * BSTR_NN + c4;
            unsigned* ph = &BsH[off];
            unsigned* pl = &BsL[off];
            split_tf32(br[i].x, ph[0], pl[0]);
            split_tf32(br[i].y, ph[1], pl[1]);
            split_tf32(br[i].z, ph[2], pl[2]);
            split_tf32(br[i].w, ph[3], pl[3]);
        }
        __syncthreads();

        #pragma unroll
        for (int ks = 0; ks < 4; ks++) {
            const int kk = ks * 8;
            unsigned aH[2][4], aL[2][4];
            #pragma unroll
            for (int i = 0; i < 2; i++) {
                const int mr = wm + i * 16;
                const int o0 = (mr + gid    ) * ASTR + kk + tig;
                const int o1 = (mr + gid + 8) * ASTR + kk + tig;
                aH[i][0] = AsH[o0];     aL[i][0] = AsL[o0];
                aH[i][1] = AsH[o1];     aL[i][1] = AsL[o1];
                aH[i][2] = AsH[o0 + 4]; aL[i][2] = AsL[o0 + 4];
                aH[i][3] = AsH[o1 + 4]; aL[i][3] = AsL[o1 + 4];
            }
            unsigned bH[4][2], bL[4][2];
            #pragma unroll
            for (int j = 0; j < 4; j++) {
                const int nc = wn + j * 8 + gid;
                int o0 = (kk + tig) * BSTR_NN + nc;
                int o1 = o0 + 4 * BSTR_NN;
                bH[j][0] = BsH[o0]; bL[j][0] = BsL[o0];
                bH[j][1] = BsH[o1]; bL[j][1] = BsL[o1];
            }
            #pragma unroll
            for (int i = 0; i < 2; i++)
                #pragma unroll
                for (int j = 0; j < 4; j++) {
                    mma_tf32(acc[i][j], aL[i], bH[j]);
                    mma_tf32(acc[i][j], aH[i], bL[j]);
                    mma_tf32(acc[i][j], aH[i], bH[j]);
                }
        }
        __syncthreads();
    }

    #pragma unroll
    for (int i = 0; i < 2; i++)
        #pragma unroll
        for (int j = 0; j < 4; j++) {
            const int r0 = m0 + wm + i * 16 + gid;
            const int c0 = n0 + wn + j * 8 + tig * 2;
            *(float2*)&C[(size_t)r0 * N + c0] =
                make_float2(acc[i][j][0], acc[i][j][1]);
            *(float2*)&C[(size_t)(r0 + 8) * N + c0] =
                make_float2(acc[i][j][2], acc[i][j][3]);
        }
}

// ---------------- merge per-tile softmax partials -> per-row (M, 1/L) --------
__global__ void softmax_merge(const float* __restrict__ smpart,
                              float2* __restrict__ ml)
{
    const int idx = blockIdx.x * 256 + threadIdx.x;   // bh*SS + row
    const float* p = smpart + (size_t)idx * NTILE * 2;
    float M = -INFINITY;
    #pragma unroll
    for (int i = 0; i < NTILE; i++) M = fmaxf(M, p[i*2]);
    float L = 0.f;
    #pragma unroll
    for (int i = 0; i < NTILE; i++) L += p[i*2+1] * __expf(p[i*2] - M);
    ml[idx] = make_float2(M, 1.f / L);
}

// ---------------- batchnorm normalize: dst = norm(src) -----------------------
__global__ void bn_norm(const float* __restrict__ src, float* __restrict__ dst,
                        const float* __restrict__ part,
                        const float* __restrict__ gamma, const float* __restrict__ beta,
                        int gstride)
{
    const int c = threadIdx.x;
    const int h = blockIdx.y;
    const int chunk = blockIdx.x;
    const float* p = part + (size_t)h * NCH * VV * 2;
    float sum = 0.f, sq = 0.f;
    #pragma unroll
    for (int j = 0; j < NCH; j++) {
        sum += p[((size_t)j*VV + c)*2 + 0];
        sq  += p[((size_t)j*VV + c)*2 + 1];
    }
    const float mean = sum * (1.f / BS);
    const float var  = sq  * (1.f / BS) - mean * mean;
    const float inv  = rsqrtf(var + EPS);
    const float g = gamma[(size_t)h * gstride + c];
    const float b = beta [(size_t)h * gstride + c];
    const float sc = inv * g;
    const float sh = b - mean * sc;
    const float* sbase = src + (size_t)h * BS * VV;
    float*       dbase = dst + (size_t)h * BS * VV;
    const int r0 = chunk * 128;
    for (int r = r0; r < r0 + 128; r++) {
        size_t idx = (size_t)r * VV + c;
        dbase[idx] = sbase[idx] * sc + sh;
    }
}

// ---------------- [H][B*S][V] -> [B,S,H,V] -----------------------------------
__global__ void write_out(const float* __restrict__ net, float* __restrict__ out)
{
    const int h = blockIdx.y, row = blockIdx.x, c = threadIdx.x;
    out[((size_t)row * HH + h) * VV + c] =
        net[(size_t)h * BS * VV + (size_t)row * VV + c];
}

// ---------------- launcher ---------------------------------------------------
extern "C" void kernel_launch(void* const* d_in, const int* in_sizes, int n_in,
                              void* d_out, int out_size)
{
    const float* x     = (const float*)d_in[0];
    const float* W_in  = (const float*)d_in[1];
    const float* Wq    = (const float*)d_in[2];
    const float* Wk    = (const float*)d_in[3];
    const float* Wv    = (const float*)d_in[4];
    const float* Wd    = (const float*)d_in[5];
    const float* g1    = (const float*)d_in[6];
    const float* b1    = (const float*)d_in[7];
    const float* g2    = (const float*)d_in[8];
    const float* b2    = (const float*)d_in[9];
    float* out = (float*)d_out;

    float *net, *q, *k, *v, *scores, *z, *part, *smpart;
    float2* ml;
    cudaGetSymbolAddress((void**)&net,    g_net);
    cudaGetSymbolAddress((void**)&q,      g_q);
    cudaGetSymbolAddress((void**)&k,      g_k);
    cudaGetSymbolAddress((void**)&v,      g_v);
    cudaGetSymbolAddress((void**)&scores, g_scores);
    cudaGetSymbolAddress((void**)&z,      g_z);
    cudaGetSymbolAddress((void**)&part,   g_part);
    cudaGetSymbolAddress((void**)&smpart, g_smpart);
    cudaGetSymbolAddress((void**)&ml,     g_ml);

    const int smem_bytes = SMEM_U32 * 4;   // 55296
    static int configured = 0;
    if (!configured) {
        cudaFuncSetAttribute(gemm_mma<0,0,0>, cudaFuncAttributeMaxDynamicSharedMemorySize, smem_bytes);
        cudaFuncSetAttribute(gemm_mma<1,3,0>, cudaFuncAttributeMaxDynamicSharedMemorySize, smem_bytes);
        cudaFuncSetAttribute(gemm_mma<0,1,1>, cudaFuncAttributeMaxDynamicSharedMemorySize, smem_bytes);
        cudaFuncSetAttribute(gemm_mma<0,2,0>, cudaFuncAttributeMaxDynamicSharedMemorySize, smem_bytes);
        cudaFuncSetAttribute(gemm_qkv,        cudaFuncAttributeMaxDynamicSharedMemorySize, smem_bytes);
        configured = 1;
    }

    const float scale = 0.125f;   // KD^-0.5

    // net[h] = x @ W_in, replicated to all 8 heads
    gemm_mma<0,0,0><<<dim3(VV/GBN, BS/GBM, 1), 256, smem_bytes>>>(
        x, W_in, net, nullptr, nullptr, nullptr, nullptr, BS, VV, DIN,
        0, 0, 0, 0, 1.f, HH, (long long)BS*VV);

    for (int t = 0; t < TT; t++) {
        // q, k, v in one launch
        gemm_qkv<<<dim3(6, BS/GBM, HH), 256, smem_bytes>>>(
            net, Wq + (size_t)t*VV*KDIM, Wk + (size_t)t*VV*KDIM,
            Wv + (size_t)t*VV*VV, q, k, v);

        // scores = scale * q @ k^T  + per-tile softmax partials
        gemm_mma<1,3,0><<<dim3(SS/GBN, SS/GBM, HH*BB), 256, smem_bytes>>>(
            q, k, scores, nullptr, nullptr, smpart, nullptr, SS, SS, KDIM,
            (long long)SS*KDIM, (long long)SS*KDIM, (long long)SS*SS, 0,
            scale, 1, 0);

        // merge partials -> per-row (M, 1/L)
        softmax_merge<<<HH*BB*SS/256, 256>>>(smpart, ml);

        // net = net + P @ v (P computed in A-loader), stats -> part
        gemm_mma<0,1,1><<<dim3(VV/GBN, SS/GBM, HH*BB), 256, smem_bytes>>>(
            scores, v, net, net, part, nullptr, ml, SS, VV, SS,
            (long long)SS*SS, (long long)SS*VV, (long long)SS*VV, (long long)SS*VV,
            1.f, 1, 0);
        bn_norm<<<dim3(NCH, HH), 256>>>(net, net, part,
            g1 + (size_t)t*VV, b1 + (size_t)t*VV, TT*VV);

        // z = net + relu(net @ Wd), stats -> part; net = BN(z)
        gemm_mma<0,2,0><<<dim3(VV/GBN, BS/GBM, HH), 256, smem_bytes>>>(
            net, Wd + (size_t)t*VV*VV, z, net, part, nullptr, nullptr, BS, VV, VV,
            (long long)BS*VV, (long long)TT*VV*VV, (long long)BS*VV, (long long)BS*VV,
            1.f, 1, 0);
        bn_norm<<<dim3(NCH, HH), 256>>>(z, net, part,
            g2 + (size_t)t*VV, b2 + (size_t)t*VV, TT*VV);
    }

    write_out<<<dim3(BS, HH), 256>>>(net, out);
}

// round 14
// speedup vs baseline: 1.5103x; 1.5103x over previous
#include <cuda_runtime.h>
#include <cuda_bf16.h>
#include <math.h>

// Problem constants
#define BB   4
#define SS   1024
#define DIN  256
#define VV   256
#define KDIM 64
#define HH   8
#define TT   4
#define BS   (BB*SS)          // 4096
#define NCH  32               // stat chunks per head
#define EPS  1e-3f

// ---------------- scratch (device globals; no allocation allowed) -----------
__device__ float g_net[HH*BS*VV];
__device__ float g_q[HH*BS*KDIM];
__device__ float g_k[HH*BS*KDIM];
__device__ float g_v[HH*BS*VV];
__device__ float g_scores[(size_t)HH*BB*SS*SS];  // 134MB
__device__ float g_z[HH*BS*VV];
__device__ float g_part[HH*NCH*VV*2];

// ---------------- TF32 helpers ----------------------------------------------
__device__ __forceinline__ unsigned f2tf(float f) {
    unsigned r;
    asm("cvt.rna.tf32.f32 %0, %1;" : "=r"(r) : "f"(f));
    return r;
}

__device__ __forceinline__ void split_tf32(float f, unsigned &hi, unsigned &lo) {
    hi = f2tf(f);
    lo = f2tf(f - __uint_as_float(hi));
}

__device__ __forceinline__ void mma_tf32(float c[4],
                                         const unsigned a[4],
                                         const unsigned b[2]) {
    asm volatile(
        "mma.sync.aligned.m16n8k8.row.col.f32.tf32.tf32.f32 "
        "{%0,%1,%2,%3}, {%4,%5,%6,%7}, {%8,%9}, {%0,%1,%2,%3};"
        : "+f"(c[0]), "+f"(c[1]), "+f"(c[2]), "+f"(c[3])
        : "r"(a[0]), "r"(a[1]), "r"(a[2]), "r"(a[3]), "r"(b[0]), "r"(b[1]));
}

// ---------------- 3xTF32 tensor-core GEMM core (R8-proven) -------------------
#define GBM 128
#define GBN 64
#define GBK 32
#define ASTR 36
#define BSTR_NN 72
#define BSTR_NT 36
#define A_TILE (GBM*ASTR)
#define B_TILE 2304
#define SMEM_U32 (2*A_TILE + 2*B_TILE)   // 13824 u32 = 55296 B

// EPI: 0 = plain C=alpha*acc (with rep); 1 = attnout fuse: y=R+acc, C=y, stats
//      (h=z>>2, chunk=(z&3)*8+by); 2 = Wd fuse: y=R+relu(acc), C=y, stats
//      (h=z, chunk=by)
template<int NT, int EPI>
__global__ void __launch_bounds__(256)
gemm_mma(const float* __restrict__ A, const float* __restrict__ B,
         float* __restrict__ C, const float* __restrict__ R,
         float* __restrict__ part,
         int M, int N, int K,
         long long sA, long long sB, long long sC, long long sR,
         float alpha, int rep, long long repStride)
{
    A += (long long)blockIdx.z * sA;
    B += (long long)blockIdx.z * sB;
    C += (long long)blockIdx.z * sC;
    if (EPI) R += (long long)blockIdx.z * sR;

    extern __shared__ unsigned smem[];
    unsigned* AsH = smem;
    unsigned* AsL = smem + A_TILE;
    unsigned* BsH = smem + 2*A_TILE;
    unsigned* BsL = smem + 2*A_TILE + B_TILE;

    const int t    = threadIdx.x;
    const int lane = t & 31;
    const int wid  = t >> 5;
    const int gid  = lane >> 2;
    const int tig  = lane & 3;
    const int wm   = (wid & 3) * 32;
    const int wn   = (wid >> 2) * 32;
    const int m0 = blockIdx.y * GBM, n0 = blockIdx.x * GBN;

    float acc[2][4][4] = {};

    for (int k0 = 0; k0 < K; k0 += GBK) {
        float4 ar[4];
        #pragma unroll
        for (int i = 0; i < 4; i++) {
            int idx = t + i * 256;
            int r = idx >> 3, c4 = (idx & 7) << 2;
            ar[i] = *(const float4*)&A[(size_t)(m0 + r) * K + k0 + c4];
        }
        float4 br[2];
        #pragma unroll
        for (int i = 0; i < 2; i++) {
            int idx = t + i * 256;
            if (NT) {
                int r = idx >> 3, c4 = (idx & 7) << 2;
                br[i] = *(const float4*)&B[(size_t)(n0 + r) * K + k0 + c4];
            } else {
                int r = idx >> 4, c4 = (idx & 15) << 2;
                br[i] = *(const float4*)&B[(size_t)(k0 + r) * N + n0 + c4];
            }
        }
        __syncthreads();
        #pragma unroll
        for (int i = 0; i < 4; i++) {
            int idx = t + i * 256;
            int r = idx >> 3, c4 = (idx & 7) << 2;
            unsigned* ph = &AsH[r * ASTR + c4];
            unsigned* pl = &AsL[r * ASTR + c4];
            split_tf32(ar[i].x, ph[0], pl[0]);
            split_tf32(ar[i].y, ph[1], pl[1]);
            split_tf32(ar[i].z, ph[2], pl[2]);
            split_tf32(ar[i].w, ph[3], pl[3]);
        }
        #pragma unroll
        for (int i = 0; i < 2; i++) {
            int idx = t + i * 256;
            int off;
            if (NT) { int r = idx >> 3, c4 = (idx & 7) << 2;  off = r * BSTR_NT + c4; }
            else    { int r = idx >> 4, c4 = (idx & 15) << 2; off = r * BSTR_NN + c4; }
            unsigned* ph = &BsH[off];
            unsigned* pl = &BsL[off];
            split_tf32(br[i].x, ph[0], pl[0]);
            split_tf32(br[i].y, ph[1], pl[1]);
            split_tf32(br[i].z, ph[2], pl[2]);
            split_tf32(br[i].w, ph[3], pl[3]);
        }
        __syncthreads();

        #pragma unroll
        for (int ks = 0; ks < 4; ks++) {
            const int kk = ks * 8;
            unsigned aH[2][4], aL[2][4];
            #pragma unroll
            for (int i = 0; i < 2; i++) {
                const int mr = wm + i * 16;
                const int o0 = (mr + gid    ) * ASTR + kk + tig;
                const int o1 = (mr + gid + 8) * ASTR + kk + tig;
                aH[i][0] = AsH[o0];     aL[i][0] = AsL[o0];
                aH[i][1] = AsH[o1];     aL[i][1] = AsL[o1];
                aH[i][2] = AsH[o0 + 4]; aL[i][2] = AsL[o0 + 4];
                aH[i][3] = AsH[o1 + 4]; aL[i][3] = AsL[o1 + 4];
            }
            unsigned bH[4][2], bL[4][2];
            #pragma unroll
            for (int j = 0; j < 4; j++) {
                const int nc = wn + j * 8 + gid;
                int o0, o1;
                if (NT) { o0 = nc * BSTR_NT + kk + tig;  o1 = o0 + 4; }
                else    { o0 = (kk + tig) * BSTR_NN + nc; o1 = o0 + 4 * BSTR_NN; }
                bH[j][0] = BsH[o0]; bL[j][0] = BsL[o0];
                bH[j][1] = BsH[o1]; bL[j][1] = BsL[o1];
            }
            #pragma unroll
            for (int i = 0; i < 2; i++)
                #pragma unroll
                for (int j = 0; j < 4; j++) {
                    mma_tf32(acc[i][j], aL[i], bH[j]);
                    mma_tf32(acc[i][j], aH[i], bL[j]);
                    mma_tf32(acc[i][j], aH[i], bH[j]);
                }
        }
        __syncthreads();
    }

    if (EPI == 0) {
        #pragma unroll
        for (int i = 0; i < 2; i++)
            #pragma unroll
            for (int j = 0; j < 4; j++) {
                const int r0 = m0 + wm + i * 16 + gid;
                const int c0 = n0 + wn + j * 8 + tig * 2;
                float2 v01 = make_float2(acc[i][j][0] * alpha, acc[i][j][1] * alpha);
                float2 v23 = make_float2(acc[i][j][2] * alpha, acc[i][j][3] * alpha);
                for (int r = 0; r < rep; r++) {
                    *(float2*)&C[(size_t)r0 * N + c0 + (size_t)r * repStride] = v01;
                    *(float2*)&C[(size_t)(r0 + 8) * N + c0 + (size_t)r * repStride] = v23;
                }
            }
    } else {
        // y = R + (relu?)(acc); C = y; per-block column stats -> part
        float colsum[8] = {}, colsq[8] = {};
        #pragma unroll
        for (int i = 0; i < 2; i++)
            #pragma unroll
            for (int j = 0; j < 4; j++) {
                const int r0 = m0 + wm + i * 16 + gid;
                const int c0 = n0 + wn + j * 8 + tig * 2;
                float2 a0 = *(const float2*)&R[(size_t)r0 * N + c0];
                float2 a1 = *(const float2*)&R[(size_t)(r0 + 8) * N + c0];
                float v0 = acc[i][j][0], v1 = acc[i][j][1];
                float v2 = acc[i][j][2], v3 = acc[i][j][3];
                if (EPI == 2) {
                    v0 = fmaxf(v0, 0.f); v1 = fmaxf(v1, 0.f);
                    v2 = fmaxf(v2, 0.f); v3 = fmaxf(v3, 0.f);
                }
                float y00 = a0.x + v0, y01 = a0.y + v1;
                float y10 = a1.x + v2, y11 = a1.y + v3;
                *(float2*)&C[(size_t)r0 * N + c0]       = make_float2(y00, y01);
                *(float2*)&C[(size_t)(r0 + 8) * N + c0] = make_float2(y10, y11);
                colsum[j*2+0] += y00 + y10;
                colsum[j*2+1] += y01 + y11;
                colsq [j*2+0] += y00*y00 + y10*y10;
                colsq [j*2+1] += y01*y01 + y11*y11;
            }
        #pragma unroll
        for (int c8 = 0; c8 < 8; c8++) {
            #pragma unroll
            for (int msk = 4; msk <= 16; msk <<= 1) {
                colsum[c8] += __shfl_xor_sync(0xffffffffu, colsum[c8], msk);
                colsq [c8] += __shfl_xor_sync(0xffffffffu, colsq [c8], msk);
            }
        }
        float* sred = (float*)smem;   // [4 m-warps][64 cols][2]
        if (gid == 0) {
            #pragma unroll
            for (int j = 0; j < 4; j++)
                #pragma unroll
                for (int e = 0; e < 2; e++) {
                    int col = wn + j * 8 + tig * 2 + e;
                    int idx = ((wid & 3) * 64 + col) * 2;
                    sred[idx + 0] = colsum[j*2+e];
                    sred[idx + 1] = colsq [j*2+e];
                }
        }
        __syncthreads();
        if (t < 64) {
            float s = 0.f, q2 = 0.f;
            #pragma unroll
            for (int w = 0; w < 4; w++) {
                s  += sred[(w * 64 + t) * 2 + 0];
                q2 += sred[(w * 64 + t) * 2 + 1];
            }
            int hh, chunk;
            if (EPI == 1) { hh = blockIdx.z >> 2; chunk = (blockIdx.z & 3) * 8 + blockIdx.y; }
            else          { hh = blockIdx.z;      chunk = blockIdx.y; }
            size_t p = ((size_t)(hh * NCH + chunk) * VV + (n0 + t)) * 2;
            part[p + 0] = s;
            part[p + 1] = q2;
        }
    }
}

// ---------------- fused q/k/v projection (one launch) ------------------------
// grid: (6, BS/GBM, HH). bx=0 -> q, bx=1 -> k, bx>=2 -> v col-block (bx-2).
__global__ void __launch_bounds__(256)
gemm_qkv(const float* __restrict__ net,
         const float* __restrict__ Wq_t, const float* __restrict__ Wk_t,
         const float* __restrict__ Wv_t,
         float* __restrict__ q, float* __restrict__ k, float* __restrict__ v)
{
    const int h = blockIdx.z;
    const int bx = blockIdx.x;
    const float* A = net + (size_t)h * BS * VV;
    const float* B;
    float* C;
    int N, n0;
    if (bx == 0)      { B = Wq_t + (size_t)h * TT * VV * KDIM; C = q + (size_t)h * BS * KDIM; N = KDIM; n0 = 0; }
    else if (bx == 1) { B = Wk_t + (size_t)h * TT * VV * KDIM; C = k + (size_t)h * BS * KDIM; N = KDIM; n0 = 0; }
    else              { B = Wv_t + (size_t)h * TT * VV * VV;   C = v + (size_t)h * BS * VV;   N = VV;   n0 = (bx - 2) * GBN; }
    const int K = VV;

    extern __shared__ unsigned smem[];
    unsigned* AsH = smem;
    unsigned* AsL = smem + A_TILE;
    unsigned* BsH = smem + 2*A_TILE;
    unsigned* BsL = smem + 2*A_TILE + B_TILE;

    const int t    = threadIdx.x;
    const int lane = t & 31;
    const int wid  = t >> 5;
    const int gid  = lane >> 2;
    const int tig  = lane & 3;
    const int wm   = (wid & 3) * 32;
    const int wn   = (wid >> 2) * 32;
    const int m0 = blockIdx.y * GBM;

    float acc[2][4][4] = {};

    for (int k0 = 0; k0 < K; k0 += GBK) {
        float4 ar[4];
        #pragma unroll
        for (int i = 0; i < 4; i++) {
            int idx = t + i * 256;
            int r = idx >> 3, c4 = (idx & 7) << 2;
            ar[i] = *(const float4*)&A[(size_t)(m0 + r) * K + k0 + c4];
        }
        float4 br[2];
        #pragma unroll
        for (int i = 0; i < 2; i++) {
            int idx = t + i * 256;
            int r = idx >> 4, c4 = (idx & 15) << 2;
            br[i] = *(const float4*)&B[(size_t)(k0 + r) * N + n0 + c4];
        }
        __syncthreads();
        #pragma unroll
        for (int i = 0; i < 4; i++) {
            int idx = t + i * 256;
            int r = idx >> 3, c4 = (idx & 7) << 2;
            unsigned* ph = &AsH[r * ASTR + c4];
            unsigned* pl = &AsL[r * ASTR + c4];
            split_tf32(ar[i].x, ph[0], pl[0]);
            split_tf32(ar[i].y, ph[1], pl[1]);
            split_tf32(ar[i].z, ph[2], pl[2]);
            split_tf32(ar[i].w, ph[3], pl[3]);
        }
        #pragma unroll
        for (int i = 0; i < 2; i++) {
            int idx = t + i * 256;
            int r = idx >> 4, c4 = (idx & 15) << 2;
            int off = r * BSTR_NN + c4;
            unsigned* ph = &BsH[off];
            unsigned* pl = &BsL[off];
            split_tf32(br[i].x, ph[0], pl[0]);
            split_tf32(br[i].y, ph[1], pl[1]);
            split_tf32(br[i].z, ph[2], pl[2]);
            split_tf32(br[i].w, ph[3], pl[3]);
        }
        __syncthreads();

        #pragma unroll
        for (int ks = 0; ks < 4; ks++) {
            const int kk = ks * 8;
            unsigned aH[2][4], aL[2][4];
            #pragma unroll
            for (int i = 0; i < 2; i++) {
                const int mr = wm + i * 16;
                const int o0 = (mr + gid    ) * ASTR + kk + tig;
                const int o1 = (mr + gid + 8) * ASTR + kk + tig;
                aH[i][0] = AsH[o0];     aL[i][0] = AsL[o0];
                aH[i][1] = AsH[o1];     aL[i][1] = AsL[o1];
                aH[i][2] = AsH[o0 + 4]; aL[i][2] = AsL[o0 + 4];
                aH[i][3] = AsH[o1 + 4]; aL[i][3] = AsL[o1 + 4];
            }
            unsigned bH[4][2], bL[4][2];
            #pragma unroll
            for (int j = 0; j < 4; j++) {
                const int nc = wn + j * 8 + gid;
                int o0 = (kk + tig) * BSTR_NN + nc;
                int o1 = o0 + 4 * BSTR_NN;
                bH[j][0] = BsH[o0]; bL[j][0] = BsL[o0];
                bH[j][1] = BsH[o1]; bL[j][1] = BsL[o1];
            }
            #pragma unroll
            for (int i = 0; i < 2; i++)
                #pragma unroll
                for (int j = 0; j < 4; j++) {
                    mma_tf32(acc[i][j], aL[i], bH[j]);
                    mma_tf32(acc[i][j], aH[i], bL[j]);
                    mma_tf32(acc[i][j], aH[i], bH[j]);
                }
        }
        __syncthreads();
    }

    #pragma unroll
    for (int i = 0; i < 2; i++)
        #pragma unroll
        for (int j = 0; j < 4; j++) {
            const int r0 = m0 + wm + i * 16 + gid;
            const int c0 = n0 + wn + j * 8 + tig * 2;
            *(float2*)&C[(size_t)r0 * N + c0] =
                make_float2(acc[i][j][0], acc[i][j][1]);
            *(float2*)&C[(size_t)(r0 + 8) * N + c0] =
                make_float2(acc[i][j][2], acc[i][j][3]);
        }
}

// ---------------- softmax: one warp per row, shuffle-only reductions ---------
__global__ void __launch_bounds__(128)
softmax_rows(float* __restrict__ s)
{
    const int warp = blockIdx.x * 4 + (threadIdx.x >> 5);
    const int lane = threadIdx.x & 31;
    float4* row = (float4*)(s + (size_t)warp * SS);

    float4 v[8];
    float m = -1e30f;
    #pragma unroll
    for (int i = 0; i < 8; i++) {
        v[i] = row[i * 32 + lane];
        m = fmaxf(m, fmaxf(fmaxf(v[i].x, v[i].y), fmaxf(v[i].z, v[i].w)));
    }
    #pragma unroll
    for (int msk = 16; msk >= 1; msk >>= 1)
        m = fmaxf(m, __shfl_xor_sync(0xffffffffu, m, msk));

    float sum = 0.f;
    #pragma unroll
    for (int i = 0; i < 8; i++) {
        v[i].x = __expf(v[i].x - m);
        v[i].y = __expf(v[i].y - m);
        v[i].z = __expf(v[i].z - m);
        v[i].w = __expf(v[i].w - m);
        sum += (v[i].x + v[i].y) + (v[i].z + v[i].w);
    }
    #pragma unroll
    for (int msk = 16; msk >= 1; msk >>= 1)
        sum += __shfl_xor_sync(0xffffffffu, sum, msk);

    const float inv = 1.f / sum;
    #pragma unroll
    for (int i = 0; i < 8; i++) {
        v[i].x *= inv; v[i].y *= inv; v[i].z *= inv; v[i].w *= inv;
        row[i * 32 + lane] = v[i];
    }
}

// ---------------- batchnorm normalize: dst = norm(src), float4 streamed ------
__global__ void __launch_bounds__(256)
bn_norm(const float* __restrict__ src, float* __restrict__ dst,
        const float* __restrict__ part,
        const float* __restrict__ gamma, const float* __restrict__ beta,
        int gstride)
{
    __shared__ float scS[VV], shS[VV];
    const int t = threadIdx.x;
    const int h = blockIdx.y;
    {
        const float* p = part + (size_t)h * NCH * VV * 2;
        float sum = 0.f, sq = 0.f;
        #pragma unroll
        for (int j = 0; j < NCH; j++) {
            sum += p[((size_t)j*VV + t)*2 + 0];
            sq  += p[((size_t)j*VV + t)*2 + 1];
        }
        const float mean = sum * (1.f / BS);
        const float var  = sq  * (1.f / BS) - mean * mean;
        const float inv  = rsqrtf(var + EPS);
        const float g = gamma[(size_t)h * gstride + t];
        const float b = beta [(size_t)h * gstride + t];
        const float sc = inv * g;
        scS[t] = sc;
        shS[t] = b - mean * sc;
    }
    __syncthreads();

    const float4* s4 = (const float4*)(src + (size_t)h * BS * VV);
    float4*       d4 = (float4*)      (dst + (size_t)h * BS * VV);
    const int total = BS * VV / 4;               // 262144
    const int stride = gridDim.x * 256;
    for (int idx = blockIdx.x * 256 + t; idx < total; idx += stride) {
        const int c4 = (idx & 63) << 2;          // 64 float4 per row
        float4 val = s4[idx];
        val.x = fmaf(val.x, scS[c4+0], shS[c4+0]);
        val.y = fmaf(val.y, scS[c4+1], shS[c4+1]);
        val.z = fmaf(val.z, scS[c4+2], shS[c4+2]);
        val.w = fmaf(val.w, scS[c4+3], shS[c4+3]);
        d4[idx] = val;
    }
}

// ---------------- [H][B*S][V] -> [B,S,H,V] -----------------------------------
__global__ void write_out(const float* __restrict__ net, float* __restrict__ out)
{
    const int h = blockIdx.y, row = blockIdx.x, c = threadIdx.x;
    out[((size_t)row * HH + h) * VV + c] =
        net[(size_t)h * BS * VV + (size_t)row * VV + c];
}

// ---------------- launcher ---------------------------------------------------
extern "C" void kernel_launch(void* const* d_in, const int* in_sizes, int n_in,
                              void* d_out, int out_size)
{
    const float* x     = (const float*)d_in[0];
    const float* W_in  = (const float*)d_in[1];
    const float* Wq    = (const float*)d_in[2];
    const float* Wk    = (const float*)d_in[3];
    const float* Wv    = (const float*)d_in[4];
    const float* Wd    = (const float*)d_in[5];
    const float* g1    = (const float*)d_in[6];
    const float* b1    = (const float*)d_in[7];
    const float* g2    = (const float*)d_in[8];
    const float* b2    = (const float*)d_in[9];
    float* out = (float*)d_out;

    float *net, *q, *k, *v, *scores, *z, *part;
    cudaGetSymbolAddress((void**)&net,    g_net);
    cudaGetSymbolAddress((void**)&q,      g_q);
    cudaGetSymbolAddress((void**)&k,      g_k);
    cudaGetSymbolAddress((void**)&v,      g_v);
    cudaGetSymbolAddress((void**)&scores, g_scores);
    cudaGetSymbolAddress((void**)&z,      g_z);
    cudaGetSymbolAddress((void**)&part,   g_part);

    const int smem_bytes = SMEM_U32 * 4;   // 55296
    static int configured = 0;
    if (!configured) {
        cudaFuncSetAttribute(gemm_mma<0,0>, cudaFuncAttributeMaxDynamicSharedMemorySize, smem_bytes);
        cudaFuncSetAttribute(gemm_mma<1,0>, cudaFuncAttributeMaxDynamicSharedMemorySize, smem_bytes);
        cudaFuncSetAttribute(gemm_mma<0,1>, cudaFuncAttributeMaxDynamicSharedMemorySize, smem_bytes);
        cudaFuncSetAttribute(gemm_mma<0,2>, cudaFuncAttributeMaxDynamicSharedMemorySize, smem_bytes);
        cudaFuncSetAttribute(gemm_qkv,      cudaFuncAttributeMaxDynamicSharedMemorySize, smem_bytes);
        configured = 1;
    }

    const float scale = 0.125f;   // KD^-0.5

    // net[h] = x @ W_in, replicated to all 8 heads
    gemm_mma<0,0><<<dim3(VV/GBN, BS/GBM, 1), 256, smem_bytes>>>(
        x, W_in, net, nullptr, nullptr, BS, VV, DIN,
        0, 0, 0, 0, 1.f, HH, (long long)BS*VV);

    for (int t = 0; t < TT; t++) {
        // q, k, v in one launch
        gemm_qkv<<<dim3(6, BS/GBM, HH), 256, smem_bytes>>>(
            net, Wq + (size_t)t*VV*KDIM, Wk + (size_t)t*VV*KDIM,
            Wv + (size_t)t*VV*VV, q, k, v);

        // scores = scale * q @ k^T, batched over (h,b) = 32
        gemm_mma<1,0><<<dim3(SS/GBN, SS/GBM, HH*BB), 256, smem_bytes>>>(
            q, k, scores, nullptr, nullptr, SS, SS, KDIM,
            (long long)SS*KDIM, (long long)SS*KDIM, (long long)SS*SS, 0,
            scale, 1, 0);

        // softmax: 1 warp per row
        softmax_rows<<<HH*BB*SS/4, 128>>>(scores);

        // net = net + scores @ v (in-place residual) + BN partial stats
        gemm_mma<0,1><<<dim3(VV/GBN, SS/GBM, HH*BB), 256, smem_bytes>>>(
            scores, v, net, net, part, SS, VV, SS,
            (long long)SS*SS, (long long)SS*VV, (long long)SS*VV, (long long)SS*VV,
            1.f, 1, 0);
        bn_norm<<<dim3(32, HH), 256>>>(net, net, part,
            g1 + (size_t)t*VV, b1 + (size_t)t*VV, TT*VV);

        // z = net + relu(net @ Wd) + BN partial stats; net = BN(z)
        gemm_mma<0,2><<<dim3(VV/GBN, BS/GBM, HH), 256, smem_bytes>>>(
            net, Wd + (size_t)t*VV*VV, z, net, part, BS, VV, VV,
            (long long)BS*VV, (long long)TT*VV*VV, (long long)BS*VV, (long long)BS*VV,
            1.f, 1, 0);
        bn_norm<<<dim3(32, HH), 256>>>(z, net, part,
            g2 + (size_t)t*VV, b2 + (size_t)t*VV, TT*VV);
    }

    write_out<<<dim3(BS, HH), 256>>>(net, out);
}

// round 15
// speedup vs baseline: 1.5195x; 1.0061x over previous
#include <cuda_runtime.h>
#include <cuda_bf16.h>
#include <math.h>

// Problem constants
#define BB   4
#define SS   1024
#define DIN  256
#define VV   256
#define KDIM 64
#define HH   8
#define TT   4
#define BS   (BB*SS)          // 4096
#define NCH  32               // stat chunks per head
#define EPS  1e-3f

// ---------------- scratch (device globals; no allocation allowed) -----------
__device__ float g_net[HH*BS*VV];
__device__ float g_q[HH*BS*KDIM];
__device__ float g_k[HH*BS*KDIM];
__device__ float g_v[HH*BS*VV];
__device__ float g_scores[(size_t)HH*BB*SS*SS];  // 134MB
__device__ float g_z[HH*BS*VV];
__device__ float g_part[HH*NCH*VV*2];

// ---------------- TF32 helpers ----------------------------------------------
__device__ __forceinline__ unsigned f2tf(float f) {
    unsigned r;
    asm("cvt.rna.tf32.f32 %0, %1;" : "=r"(r) : "f"(f));
    return r;
}

__device__ __forceinline__ void split_tf32(float f, unsigned &hi, unsigned &lo) {
    hi = f2tf(f);
    lo = f2tf(f - __uint_as_float(hi));
}

__device__ __forceinline__ void mma_tf32(float c[4],
                                         const unsigned a[4],
                                         const unsigned b[2]) {
    asm volatile(
        "mma.sync.aligned.m16n8k8.row.col.f32.tf32.tf32.f32 "
        "{%0,%1,%2,%3}, {%4,%5,%6,%7}, {%8,%9}, {%0,%1,%2,%3};"
        : "+f"(c[0]), "+f"(c[1]), "+f"(c[2]), "+f"(c[3])
        : "r"(a[0]), "r"(a[1]), "r"(a[2]), "r"(a[3]), "r"(b[0]), "r"(b[1]));
}

// ---------------- 3xTF32 tensor-core GEMM core (R8-proven dataflow) ----------
// NEW this round: __launch_bounds__(256, 4) -> 64-reg budget, 4 CTAs/SM.
#define GBM 128
#define GBN 64
#define GBK 32
#define ASTR 36
#define BSTR_NN 72
#define BSTR_NT 36
#define A_TILE (GBM*ASTR)
#define B_TILE 2304
#define SMEM_U32 (2*A_TILE + 2*B_TILE)   // 13824 u32 = 55296 B

// EPI: 0 = plain C=alpha*acc (with rep); 1 = attnout fuse: y=R+acc, C=y, stats
//      (h=z>>2, chunk=(z&3)*8+by); 2 = Wd fuse: y=R+relu(acc), C=y, stats
//      (h=z, chunk=by)
template<int NT, int EPI>
__global__ void __launch_bounds__(256, 4)
gemm_mma(const float* __restrict__ A, const float* __restrict__ B,
         float* __restrict__ C, const float* __restrict__ R,
         float* __restrict__ part,
         int M, int N, int K,
         long long sA, long long sB, long long sC, long long sR,
         float alpha, int rep, long long repStride)
{
    A += (long long)blockIdx.z * sA;
    B += (long long)blockIdx.z * sB;
    C += (long long)blockIdx.z * sC;
    if (EPI) R += (long long)blockIdx.z * sR;

    extern __shared__ unsigned smem[];
    unsigned* AsH = smem;
    unsigned* AsL = smem + A_TILE;
    unsigned* BsH = smem + 2*A_TILE;
    unsigned* BsL = smem + 2*A_TILE + B_TILE;

    const int t    = threadIdx.x;
    const int lane = t & 31;
    const int wid  = t >> 5;
    const int gid  = lane >> 2;
    const int tig  = lane & 3;
    const int wm   = (wid & 3) * 32;
    const int wn   = (wid >> 2) * 32;
    const int m0 = blockIdx.y * GBM, n0 = blockIdx.x * GBN;

    float acc[2][4][4] = {};

    for (int k0 = 0; k0 < K; k0 += GBK) {
        float4 ar[4];
        #pragma unroll
        for (int i = 0; i < 4; i++) {
            int idx = t + i * 256;
            int r = idx >> 3, c4 = (idx & 7) << 2;
            ar[i] = *(const float4*)&A[(size_t)(m0 + r) * K + k0 + c4];
        }
        float4 br[2];
        #pragma unroll
        for (int i = 0; i < 2; i++) {
            int idx = t + i * 256;
            if (NT) {
                int r = idx >> 3, c4 = (idx & 7) << 2;
                br[i] = *(const float4*)&B[(size_t)(n0 + r) * K + k0 + c4];
            } else {
                int r = idx >> 4, c4 = (idx & 15) << 2;
                br[i] = *(const float4*)&B[(size_t)(k0 + r) * N + n0 + c4];
            }
        }
        __syncthreads();
        #pragma unroll
        for (int i = 0; i < 4; i++) {
            int idx = t + i * 256;
            int r = idx >> 3, c4 = (idx & 7) << 2;
            unsigned* ph = &AsH[r * ASTR + c4];
            unsigned* pl = &AsL[r * ASTR + c4];
            split_tf32(ar[i].x, ph[0], pl[0]);
            split_tf32(ar[i].y, ph[1], pl[1]);
            split_tf32(ar[i].z, ph[2], pl[2]);
            split_tf32(ar[i].w, ph[3], pl[3]);
        }
        #pragma unroll
        for (int i = 0; i < 2; i++) {
            int idx = t + i * 256;
            int off;
            if (NT) { int r = idx >> 3, c4 = (idx & 7) << 2;  off = r * BSTR_NT + c4; }
            else    { int r = idx >> 4, c4 = (idx & 15) << 2; off = r * BSTR_NN + c4; }
            unsigned* ph = &BsH[off];
            unsigned* pl = &BsL[off];
            split_tf32(br[i].x, ph[0], pl[0]);
            split_tf32(br[i].y, ph[1], pl[1]);
            split_tf32(br[i].z, ph[2], pl[2]);
            split_tf32(br[i].w, ph[3], pl[3]);
        }
        __syncthreads();

        #pragma unroll
        for (int ks = 0; ks < 4; ks++) {
            const int kk = ks * 8;
            unsigned aH[2][4], aL[2][4];
            #pragma unroll
            for (int i = 0; i < 2; i++) {
                const int mr = wm + i * 16;
                const int o0 = (mr + gid    ) * ASTR + kk + tig;
                const int o1 = (mr + gid + 8) * ASTR + kk + tig;
                aH[i][0] = AsH[o0];     aL[i][0] = AsL[o0];
                aH[i][1] = AsH[o1];     aL[i][1] = AsL[o1];
                aH[i][2] = AsH[o0 + 4]; aL[i][2] = AsL[o0 + 4];
                aH[i][3] = AsH[o1 + 4]; aL[i][3] = AsL[o1 + 4];
            }
            unsigned bH[4][2], bL[4][2];
            #pragma unroll
            for (int j = 0; j < 4; j++) {
                const int nc = wn + j * 8 + gid;
                int o0, o1;
                if (NT) { o0 = nc * BSTR_NT + kk + tig;  o1 = o0 + 4; }
                else    { o0 = (kk + tig) * BSTR_NN + nc; o1 = o0 + 4 * BSTR_NN; }
                bH[j][0] = BsH[o0]; bL[j][0] = BsL[o0];
                bH[j][1] = BsH[o1]; bL[j][1] = BsL[o1];
            }
            #pragma unroll
            for (int i = 0; i < 2; i++)
                #pragma unroll
                for (int j = 0; j < 4; j++) {
                    mma_tf32(acc[i][j], aL[i], bH[j]);
                    mma_tf32(acc[i][j], aH[i], bL[j]);
                    mma_tf32(acc[i][j], aH[i], bH[j]);
                }
        }
        __syncthreads();
    }

    if (EPI == 0) {
        #pragma unroll
        for (int i = 0; i < 2; i++)
            #pragma unroll
            for (int j = 0; j < 4; j++) {
                const int r0 = m0 + wm + i * 16 + gid;
                const int c0 = n0 + wn + j * 8 + tig * 2;
                float2 v01 = make_float2(acc[i][j][0] * alpha, acc[i][j][1] * alpha);
                float2 v23 = make_float2(acc[i][j][2] * alpha, acc[i][j][3] * alpha);
                for (int r = 0; r < rep; r++) {
                    *(float2*)&C[(size_t)r0 * N + c0 + (size_t)r * repStride] = v01;
                    *(float2*)&C[(size_t)(r0 + 8) * N + c0 + (size_t)r * repStride] = v23;
                }
            }
    } else {
        // y = R + (relu?)(acc); C = y; per-block column stats -> part
        float colsum[8] = {}, colsq[8] = {};
        #pragma unroll
        for (int i = 0; i < 2; i++)
            #pragma unroll
            for (int j = 0; j < 4; j++) {
                const int r0 = m0 + wm + i * 16 + gid;
                const int c0 = n0 + wn + j * 8 + tig * 2;
                float2 a0 = *(const float2*)&R[(size_t)r0 * N + c0];
                float2 a1 = *(const float2*)&R[(size_t)(r0 + 8) * N + c0];
                float v0 = acc[i][j][0], v1 = acc[i][j][1];
                float v2 = acc[i][j][2], v3 = acc[i][j][3];
                if (EPI == 2) {
                    v0 = fmaxf(v0, 0.f); v1 = fmaxf(v1, 0.f);
                    v2 = fmaxf(v2, 0.f); v3 = fmaxf(v3, 0.f);
                }
                float y00 = a0.x + v0, y01 = a0.y + v1;
                float y10 = a1.x + v2, y11 = a1.y + v3;
                *(float2*)&C[(size_t)r0 * N + c0]       = make_float2(y00, y01);
                *(float2*)&C[(size_t)(r0 + 8) * N + c0] = make_float2(y10, y11);
                colsum[j*2+0] += y00 + y10;
                colsum[j*2+1] += y01 + y11;
                colsq [j*2+0] += y00*y00 + y10*y10;
                colsq [j*2+1] += y01*y01 + y11*y11;
            }
        #pragma unroll
        for (int c8 = 0; c8 < 8; c8++) {
            #pragma unroll
            for (int msk = 4; msk <= 16; msk <<= 1) {
                colsum[c8] += __shfl_xor_sync(0xffffffffu, colsum[c8], msk);
                colsq [c8] += __shfl_xor_sync(0xffffffffu, colsq [c8], msk);
            }
        }
        float* sred = (float*)smem;   // [4 m-warps][64 cols][2]
        if (gid == 0) {
            #pragma unroll
            for (int j = 0; j < 4; j++)
                #pragma unroll
                for (int e = 0; e < 2; e++) {
                    int col = wn + j * 8 + tig * 2 + e;
                    int idx = ((wid & 3) * 64 + col) * 2;
                    sred[idx + 0] = colsum[j*2+e];
                    sred[idx + 1] = colsq [j*2+e];
                }
        }
        __syncthreads();
        if (t < 64) {
            float s = 0.f, q2 = 0.f;
            #pragma unroll
            for (int w = 0; w < 4; w++) {
                s  += sred[(w * 64 + t) * 2 + 0];
                q2 += sred[(w * 64 + t) * 2 + 1];
            }
            int hh, chunk;
            if (EPI == 1) { hh = blockIdx.z >> 2; chunk = (blockIdx.z & 3) * 8 + blockIdx.y; }
            else          { hh = blockIdx.z;      chunk = blockIdx.y; }
            size_t p = ((size_t)(hh * NCH + chunk) * VV + (n0 + t)) * 2;
            part[p + 0] = s;
            part[p + 1] = q2;
        }
    }
}

// ---------------- fused q/k/v projection (one launch) ------------------------
// grid: (6, BS/GBM, HH). bx=0 -> q, bx=1 -> k, bx>=2 -> v col-block (bx-2).
__global__ void __launch_bounds__(256, 4)
gemm_qkv(const float* __restrict__ net,
         const float* __restrict__ Wq_t, const float* __restrict__ Wk_t,
         const float* __restrict__ Wv_t,
         float* __restrict__ q, float* __restrict__ k, float* __restrict__ v)
{
    const int h = blockIdx.z;
    const int bx = blockIdx.x;
    const float* A = net + (size_t)h * BS * VV;
    const float* B;
    float* C;
    int N, n0;
    if (bx == 0)      { B = Wq_t + (size_t)h * TT * VV * KDIM; C = q + (size_t)h * BS * KDIM; N = KDIM; n0 = 0; }
    else if (bx == 1) { B = Wk_t + (size_t)h * TT * VV * KDIM; C = k + (size_t)h * BS * KDIM; N = KDIM; n0 = 0; }
    else              { B = Wv_t + (size_t)h * TT * VV * VV;   C = v + (size_t)h * BS * VV;   N = VV;   n0 = (bx - 2) * GBN; }
    const int K = VV;

    extern __shared__ unsigned smem[];
    unsigned* AsH = smem;
    unsigned* AsL = smem + A_TILE;
    unsigned* BsH = smem + 2*A_TILE;
    unsigned* BsL = smem + 2*A_TILE + B_TILE;

    const int t    = threadIdx.x;
    const int lane = t & 31;
    const int wid  = t >> 5;
    const int gid  = lane >> 2;
    const int tig  = lane & 3;
    const int wm   = (wid & 3) * 32;
    const int wn   = (wid >> 2) * 32;
    const int m0 = blockIdx.y * GBM;

    float acc[2][4][4] = {};

    for (int k0 = 0; k0 < K; k0 += GBK) {
        float4 ar[4];
        #pragma unroll
        for (int i = 0; i < 4; i++) {
            int idx = t + i * 256;
            int r = idx >> 3, c4 = (idx & 7) << 2;
            ar[i] = *(const float4*)&A[(size_t)(m0 + r) * K + k0 + c4];
        }
        float4 br[2];
        #pragma unroll
        for (int i = 0; i < 2; i++) {
            int idx = t + i * 256;
            int r = idx >> 4, c4 = (idx & 15) << 2;
            br[i] = *(const float4*)&B[(size_t)(k0 + r) * N + n0 + c4];
        }
        __syncthreads();
        #pragma unroll
        for (int i = 0; i < 4; i++) {
            int idx = t + i * 256;
            int r = idx >> 3, c4 = (idx & 7) << 2;
            unsigned* ph = &AsH[r * ASTR + c4];
            unsigned* pl = &AsL[r * ASTR + c4];
            split_tf32(ar[i].x, ph[0], pl[0]);
            split_tf32(ar[i].y, ph[1], pl[1]);
            split_tf32(ar[i].z, ph[2], pl[2]);
            split_tf32(ar[i].w, ph[3], pl[3]);
        }
        #pragma unroll
        for (int i = 0; i < 2; i++) {
            int idx = t + i * 256;
            int r = idx >> 4, c4 = (idx & 15) << 2;
            int off = r * BSTR_NN + c4;
            unsigned* ph = &BsH[off];
            unsigned* pl = &BsL[off];
            split_tf32(br[i].x, ph[0], pl[0]);
            split_tf32(br[i].y, ph[1], pl[1]);
            split_tf32(br[i].z, ph[2], pl[2]);
            split_tf32(br[i].w, ph[3], pl[3]);
        }
        __syncthreads();

        #pragma unroll
        for (int ks = 0; ks < 4; ks++) {
            const int kk = ks * 8;
            unsigned aH[2][4], aL[2][4];
            #pragma unroll
            for (int i = 0; i < 2; i++) {
                const int mr = wm + i * 16;
                const int o0 = (mr + gid    ) * ASTR + kk + tig;
                const int o1 = (mr + gid + 8) * ASTR + kk + tig;
                aH[i][0] = AsH[o0];     aL[i][0] = AsL[o0];
                aH[i][1] = AsH[o1];     aL[i][1] = AsL[o1];
                aH[i][2] = AsH[o0 + 4]; aL[i][2] = AsL[o0 + 4];
                aH[i][3] = AsH[o1 + 4]; aL[i][3] = AsL[o1 + 4];
            }
            unsigned bH[4][2], bL[4][2];
            #pragma unroll
            for (int j = 0; j < 4; j++) {
                const int nc = wn + j * 8 + gid;
                int o0 = (kk + tig) * BSTR_NN + nc;
                int o1 = o0 + 4 * BSTR_NN;
                bH[j][0] = BsH[o0]; bL[j][0] = BsL[o0];
                bH[j][1] = BsH[o1]; bL[j][1] = BsL[o1];
            }
            #pragma unroll
            for (int i = 0; i < 2; i++)
                #pragma unroll
                for (int j = 0; j < 4; j++) {
                    mma_tf32(acc[i][j], aL[i], bH[j]);
                    mma_tf32(acc[i][j], aH[i], bL[j]);
                    mma_tf32(acc[i][j], aH[i], bH[j]);
                }
        }
        __syncthreads();
    }

    #pragma unroll
    for (int i = 0; i < 2; i++)
        #pragma unroll
        for (int j = 0; j < 4; j++) {
            const int r0 = m0 + wm + i * 16 + gid;
            const int c0 = n0 + wn + j * 8 + tig * 2;
            *(float2*)&C[(size_t)r0 * N + c0] =
                make_float2(acc[i][j][0], acc[i][j][1]);
            *(float2*)&C[(size_t)(r0 + 8) * N + c0] =
                make_float2(acc[i][j][2], acc[i][j][3]);
        }
}

// ---------------- softmax: one warp per row, shuffle-only reductions ---------
__global__ void __launch_bounds__(128)
softmax_rows(float* __restrict__ s)
{
    const int warp = blockIdx.x * 4 + (threadIdx.x >> 5);
    const int lane = threadIdx.x & 31;
    float4* row = (float4*)(s + (size_t)warp * SS);

    float4 v[8];
    float m = -1e30f;
    #pragma unroll
    for (int i = 0; i < 8; i++) {
        v[i] = row[i * 32 + lane];
        m = fmaxf(m, fmaxf(fmaxf(v[i].x, v[i].y), fmaxf(v[i].z, v[i].w)));
    }
    #pragma unroll
    for (int msk = 16; msk >= 1; msk >>= 1)
        m = fmaxf(m, __shfl_xor_sync(0xffffffffu, m, msk));

    float sum = 0.f;
    #pragma unroll
    for (int i = 0; i < 8; i++) {
        v[i].x = __expf(v[i].x - m);
        v[i].y = __expf(v[i].y - m);
        v[i].z = __expf(v[i].z - m);
        v[i].w = __expf(v[i].w - m);
        sum += (v[i].x + v[i].y) + (v[i].z + v[i].w);
    }
    #pragma unroll
    for (int msk = 16; msk >= 1; msk >>= 1)
        sum += __shfl_xor_sync(0xffffffffu, sum, msk);

    const float inv = 1.f / sum;
    #pragma unroll
    for (int i = 0; i < 8; i++) {
        v[i].x *= inv; v[i].y *= inv; v[i].z *= inv; v[i].w *= inv;
        row[i * 32 + lane] = v[i];
    }
}

// ---------------- batchnorm normalize: dst = norm(src), float4 streamed ------
__global__ void __launch_bounds__(256)
bn_norm(const float* __restrict__ src, float* __restrict__ dst,
        const float* __restrict__ part,
        const float* __restrict__ gamma, const float* __restrict__ beta,
        int gstride)
{
    __shared__ float scS[VV], shS[VV];
    const int t = threadIdx.x;
    const int h = blockIdx.y;
    {
        const float* p = part + (size_t)h * NCH * VV * 2;
        float sum = 0.f, sq = 0.f;
        #pragma unroll
        for (int j = 0; j < NCH; j++) {
            sum += p[((size_t)j*VV + t)*2 + 0];
            sq  += p[((size_t)j*VV + t)*2 + 1];
        }
        const float mean = sum * (1.f / BS);
        const float var  = sq  * (1.f / BS) - mean * mean;
        const float inv  = rsqrtf(var + EPS);
        const float g = gamma[(size_t)h * gstride + t];
        const float b = beta [(size_t)h * gstride + t];
        const float sc = inv * g;
        scS[t] = sc;
        shS[t] = b - mean * sc;
    }
    __syncthreads();

    const float4* s4 = (const float4*)(src + (size_t)h * BS * VV);
    float4*       d4 = (float4*)      (dst + (size_t)h * BS * VV);
    const int total = BS * VV / 4;               // 262144
    const int stride = gridDim.x * 256;
    for (int idx = blockIdx.x * 256 + t; idx < total; idx += stride) {
        const int c4 = (idx & 63) << 2;          // 64 float4 per row
        float4 val = s4[idx];
        val.x = fmaf(val.x, scS[c4+0], shS[c4+0]);
        val.y = fmaf(val.y, scS[c4+1], shS[c4+1]);
        val.z = fmaf(val.z, scS[c4+2], shS[c4+2]);
        val.w = fmaf(val.w, scS[c4+3], shS[c4+3]);
        d4[idx] = val;
    }
}

// ---------------- [H][B*S][V] -> [B,S,H,V], float4 ---------------------------
__global__ void __launch_bounds__(256)
write_out(const float* __restrict__ net, float* __restrict__ out)
{
    const int h = blockIdx.y;
    const int row = blockIdx.x * 4 + (threadIdx.x >> 6);
    const int c4 = threadIdx.x & 63;
    const float4* n4 = (const float4*)(net + (size_t)h * BS * VV);
    float4* o4 = (float4*)out;
    o4[((size_t)row * HH + h) * 64 + c4] = n4[(size_t)row * 64 + c4];
}

// ---------------- launcher ---------------------------------------------------
extern "C" void kernel_launch(void* const* d_in, const int* in_sizes, int n_in,
                              void* d_out, int out_size)
{
    const float* x     = (const float*)d_in[0];
    const float* W_in  = (const float*)d_in[1];
    const float* Wq    = (const float*)d_in[2];
    const float* Wk    = (const float*)d_in[3];
    const float* Wv    = (const float*)d_in[4];
    const float* Wd    = (const float*)d_in[5];
    const float* g1    = (const float*)d_in[6];
    const float* b1    = (const float*)d_in[7];
    const float* g2    = (const float*)d_in[8];
    const float* b2    = (const float*)d_in[9];
    float* out = (float*)d_out;

    float *net, *q, *k, *v, *scores, *z, *part;
    cudaGetSymbolAddress((void**)&net,    g_net);
    cudaGetSymbolAddress((void**)&q,      g_q);
    cudaGetSymbolAddress((void**)&k,      g_k);
    cudaGetSymbolAddress((void**)&v,      g_v);
    cudaGetSymbolAddress((void**)&scores, g_scores);
    cudaGetSymbolAddress((void**)&z,      g_z);
    cudaGetSymbolAddress((void**)&part,   g_part);

    const int smem_bytes = SMEM_U32 * 4;   // 55296
    static int configured = 0;
    if (!configured) {
        cudaFuncSetAttribute(gemm_mma<0,0>, cudaFuncAttributeMaxDynamicSharedMemorySize, smem_bytes);
        cudaFuncSetAttribute(gemm_mma<1,0>, cudaFuncAttributeMaxDynamicSharedMemorySize, smem_bytes);
        cudaFuncSetAttribute(gemm_mma<0,1>, cudaFuncAttributeMaxDynamicSharedMemorySize, smem_bytes);
        cudaFuncSetAttribute(gemm_mma<0,2>, cudaFuncAttributeMaxDynamicSharedMemorySize, smem_bytes);
        cudaFuncSetAttribute(gemm_qkv,      cudaFuncAttributeMaxDynamicSharedMemorySize, smem_bytes);
        configured = 1;
    }

    const float scale = 0.125f;   // KD^-0.5

    // net[h] = x @ W_in, replicated to all 8 heads
    gemm_mma<0,0><<<dim3(VV/GBN, BS/GBM, 1), 256, smem_bytes>>>(
        x, W_in, net, nullptr, nullptr, BS, VV, DIN,
        0, 0, 0, 0, 1.f, HH, (long long)BS*VV);

    for (int t = 0; t < TT; t++) {
        // q, k, v in one launch
        gemm_qkv<<<dim3(6, BS/GBM, HH), 256, smem_bytes>>>(
            net, Wq + (size_t)t*VV*KDIM, Wk + (size_t)t*VV*KDIM,
            Wv + (size_t)t*VV*VV, q, k, v);

        // scores = scale * q @ k^T, batched over (h,b) = 32
        gemm_mma<1,0><<<dim3(SS/GBN, SS/GBM, HH*BB), 256, smem_bytes>>>(
            q, k, scores, nullptr, nullptr, SS, SS, KDIM,
            (long long)SS*KDIM, (long long)SS*KDIM, (long long)SS*SS, 0,
            scale, 1, 0);

        // softmax: 1 warp per row
        softmax_rows<<<HH*BB*SS/4, 128>>>(scores);

        // net = net + scores @ v (in-place residual) + BN partial stats
        gemm_mma<0,1><<<dim3(VV/GBN, SS/GBM, HH*BB), 256, smem_bytes>>>(
            scores, v, net, net, part, SS, VV, SS,
            (long long)SS*SS, (long long)SS*VV, (long long)SS*VV, (long long)SS*VV,
            1.f, 1, 0);
        bn_norm<<<dim3(32, HH), 256>>>(net, net, part,
            g1 + (size_t)t*VV, b1 + (size_t)t*VV, TT*VV);

        // z = net + relu(net @ Wd) + BN partial stats; net = BN(z)
        gemm_mma<0,2><<<dim3(VV/GBN, BS/GBM, HH), 256, smem_bytes>>>(
            net, Wd + (size_t)t*VV*VV, z, net, part, BS, VV, VV,
            (long long)BS*VV, (long long)TT*VV*VV, (long long)BS*VV, (long long)BS*VV,
            1.f, 1, 0);
        bn_norm<<<dim3(32, HH), 256>>>(z, net, part,
            g2 + (size_t)t*VV, b2 + (size_t)t*VV, TT*VV);
    }

    write_out<<<dim3(BS/4, HH), 256>>>(net, out);
}

// round 17
// speedup vs baseline: 1.5531x; 1.0221x over previous
#include <cuda_runtime.h>
#include <cuda_bf16.h>
#include <math.h>

// Problem constants
#define BB   4
#define SS   1024
#define DIN  256
#define VV   256
#define KDIM 64
#define HH   8
#define TT   4
#define BS   (BB*SS)          // 4096
#define NCH  32               // stat chunks per head
#define EPS  1e-3f

// ---------------- scratch (device globals; no allocation allowed) -----------
__device__ float g_net[HH*BS*VV];
__device__ float g_q[HH*BS*KDIM];
__device__ float g_k[HH*BS*KDIM];
__device__ float g_v[HH*BS*VV];
__device__ float g_scores[(size_t)HH*BB*SS*SS];  // 134MB
__device__ float g_z[HH*BS*VV];
__device__ float g_part[HH*NCH*VV*2];

// ---------------- TF32 helpers ----------------------------------------------
__device__ __forceinline__ unsigned f2tf(float f) {
    unsigned r;
    asm("cvt.rna.tf32.f32 %0, %1;" : "=r"(r) : "f"(f));
    return r;
}

__device__ __forceinline__ void split_tf32(float f, unsigned &hi, unsigned &lo) {
    hi = f2tf(f);
    lo = f2tf(f - __uint_as_float(hi));
}

__device__ __forceinline__ void mma_tf32(float c[4],
                                         const unsigned a[4],
                                         const unsigned b[2]) {
    asm volatile(
        "mma.sync.aligned.m16n8k8.row.col.f32.tf32.tf32.f32 "
        "{%0,%1,%2,%3}, {%4,%5,%6,%7}, {%8,%9}, {%0,%1,%2,%3};"
        : "+f"(c[0]), "+f"(c[1]), "+f"(c[2]), "+f"(c[3])
        : "r"(a[0]), "r"(a[1]), "r"(a[2]), "r"(a[3]), "r"(b[0]), "r"(b[1]));
}

// ---------------- 3xTF32 tensor-core GEMM core (R15-proven) ------------------
#define GBM 128
#define GBN 64
#define GBK 32
#define ASTR 36
#define BSTR_NN 72
#define BSTR_NT 36
#define A_TILE (GBM*ASTR)
#define B_TILE 2304
#define SMEM_U32 (2*A_TILE + 2*B_TILE)   // 13824 u32 = 55296 B

// EPI: 0 = plain C=alpha*acc (with rep); 1 = attnout fuse: y=R+acc, C=y, stats
//      (h=z>>2, chunk=(z&3)*8+by); 2 = Wd fuse: y=R+relu(acc), C=y, stats
//      (h=z, chunk=by)
template<int NT, int EPI>
__global__ void __launch_bounds__(256, 4)
gemm_mma(const float* __restrict__ A, const float* __restrict__ B,
         float* __restrict__ C, const float* __restrict__ R,
         float* __restrict__ part,
         int M, int N, int K,
         long long sA, long long sB, long long sC, long long sR,
         float alpha, int rep, long long repStride)
{
    A += (long long)blockIdx.z * sA;
    B += (long long)blockIdx.z * sB;
    C += (long long)blockIdx.z * sC;
    if (EPI) R += (long long)blockIdx.z * sR;

    extern __shared__ unsigned smem[];
    unsigned* AsH = smem;
    unsigned* AsL = smem + A_TILE;
    unsigned* BsH = smem + 2*A_TILE;
    unsigned* BsL = smem + 2*A_TILE + B_TILE;

    const int t    = threadIdx.x;
    const int lane = t & 31;
    const int wid  = t >> 5;
    const int gid  = lane >> 2;
    const int tig  = lane & 3;
    const int wm   = (wid & 3) * 32;
    const int wn   = (wid >> 2) * 32;
    const int m0 = blockIdx.y * GBM, n0 = blockIdx.x * GBN;

    float acc[2][4][4] = {};

    for (int k0 = 0; k0 < K; k0 += GBK) {
        float4 ar[4];
        #pragma unroll
        for (int i = 0; i < 4; i++) {
            int idx = t + i * 256;
            int r = idx >> 3, c4 = (idx & 7) << 2;
            ar[i] = *(const float4*)&A[(size_t)(m0 + r) * K + k0 + c4];
        }
        float4 br[2];
        #pragma unroll
        for (int i = 0; i < 2; i++) {
            int idx = t + i * 256;
            if (NT) {
                int r = idx >> 3, c4 = (idx & 7) << 2;
                br[i] = *(const float4*)&B[(size_t)(n0 + r) * K + k0 + c4];
            } else {
                int r = idx >> 4, c4 = (idx & 15) << 2;
                br[i] = *(const float4*)&B[(size_t)(k0 + r) * N + n0 + c4];
            }
        }
        __syncthreads();
        #pragma unroll
        for (int i = 0; i < 4; i++) {
            int idx = t + i * 256;
            int r = idx >> 3, c4 = (idx & 7) << 2;
            unsigned* ph = &AsH[r * ASTR + c4];
            unsigned* pl = &AsL[r * ASTR + c4];
            split_tf32(ar[i].x, ph[0], pl[0]);
            split_tf32(ar[i].y, ph[1], pl[1]);
            split_tf32(ar[i].z, ph[2], pl[2]);
            split_tf32(ar[i].w, ph[3], pl[3]);
        }
        #pragma unroll
        for (int i = 0; i < 2; i++) {
            int idx = t + i * 256;
            int off;
            if (NT) { int r = idx >> 3, c4 = (idx & 7) << 2;  off = r * BSTR_NT + c4; }
            else    { int r = idx >> 4, c4 = (idx & 15) << 2; off = r * BSTR_NN + c4; }
            unsigned* ph = &BsH[off];
            unsigned* pl = &BsL[off];
            split_tf32(br[i].x, ph[0], pl[0]);
            split_tf32(br[i].y, ph[1], pl[1]);
            split_tf32(br[i].z, ph[2], pl[2]);
            split_tf32(br[i].w, ph[3], pl[3]);
        }
        __syncthreads();

        #pragma unroll
        for (int ks = 0; ks < 4; ks++) {
            const int kk = ks * 8;
            unsigned aH[2][4], aL[2][4];
            #pragma unroll
            for (int i = 0; i < 2; i++) {
                const int mr = wm + i * 16;
                const int o0 = (mr + gid    ) * ASTR + kk + tig;
                const int o1 = (mr + gid + 8) * ASTR + kk + tig;
                aH[i][0] = AsH[o0];     aL[i][0] = AsL[o0];
                aH[i][1] = AsH[o1];     aL[i][1] = AsL[o1];
                aH[i][2] = AsH[o0 + 4]; aL[i][2] = AsL[o0 + 4];
                aH[i][3] = AsH[o1 + 4]; aL[i][3] = AsL[o1 + 4];
            }
            unsigned bH[4][2], bL[4][2];
            #pragma unroll
            for (int j = 0; j < 4; j++) {
                const int nc = wn + j * 8 + gid;
                int o0, o1;
                if (NT) { o0 = nc * BSTR_NT + kk + tig;  o1 = o0 + 4; }
                else    { o0 = (kk + tig) * BSTR_NN + nc; o1 = o0 + 4 * BSTR_NN; }
                bH[j][0] = BsH[o0]; bL[j][0] = BsL[o0];
                bH[j][1] = BsH[o1]; bL[j][1] = BsL[o1];
            }
            #pragma unroll
            for (int i = 0; i < 2; i++)
                #pragma unroll
                for (int j = 0; j < 4; j++) {
                    mma_tf32(acc[i][j], aL[i], bH[j]);
                    mma_tf32(acc[i][j], aH[i], bL[j]);
                    mma_tf32(acc[i][j], aH[i], bH[j]);
                }
        }
        __syncthreads();
    }

    if (EPI == 0) {
        #pragma unroll
        for (int i = 0; i < 2; i++)
            #pragma unroll
            for (int j = 0; j < 4; j++) {
                const int r0 = m0 + wm + i * 16 + gid;
                const int c0 = n0 + wn + j * 8 + tig * 2;
                float2 v01 = make_float2(acc[i][j][0] * alpha, acc[i][j][1] * alpha);
                float2 v23 = make_float2(acc[i][j][2] * alpha, acc[i][j][3] * alpha);
                for (int r = 0; r < rep; r++) {
                    *(float2*)&C[(size_t)r0 * N + c0 + (size_t)r * repStride] = v01;
                    *(float2*)&C[(size_t)(r0 + 8) * N + c0 + (size_t)r * repStride] = v23;
                }
            }
    } else {
        // y = R + (relu?)(acc); C = y; per-block column stats -> part
        float colsum[8] = {}, colsq[8] = {};
        #pragma unroll
        for (int i = 0; i < 2; i++)
            #pragma unroll
            for (int j = 0; j < 4; j++) {
                const int r0 = m0 + wm + i * 16 + gid;
                const int c0 = n0 + wn + j * 8 + tig * 2;
                float2 a0 = *(const float2*)&R[(size_t)r0 * N + c0];
                float2 a1 = *(const float2*)&R[(size_t)(r0 + 8) * N + c0];
                float v0 = acc[i][j][0], v1 = acc[i][j][1];
                float v2 = acc[i][j][2], v3 = acc[i][j][3];
                if (EPI == 2) {
                    v0 = fmaxf(v0, 0.f); v1 = fmaxf(v1, 0.f);
                    v2 = fmaxf(v2, 0.f); v3 = fmaxf(v3, 0.f);
                }
                float y00 = a0.x + v0, y01 = a0.y + v1;
                float y10 = a1.x + v2, y11 = a1.y + v3;
                *(float2*)&C[(size_t)r0 * N + c0]       = make_float2(y00, y01);
                *(float2*)&C[(size_t)(r0 + 8) * N + c0] = make_float2(y10, y11);
                colsum[j*2+0] += y00 + y10;
                colsum[j*2+1] += y01 + y11;
                colsq [j*2+0] += y00*y00 + y10*y10;
                colsq [j*2+1] += y01*y01 + y11*y11;
            }
        #pragma unroll
        for (int c8 = 0; c8 < 8; c8++) {
            #pragma unroll
            for (int msk = 4; msk <= 16; msk <<= 1) {
                colsum[c8] += __shfl_xor_sync(0xffffffffu, colsum[c8], msk);
                colsq [c8] += __shfl_xor_sync(0xffffffffu, colsq [c8], msk);
            }
        }
        float* sred = (float*)smem;   // [4 m-warps][64 cols][2]
        if (gid == 0) {
            #pragma unroll
            for (int j = 0; j < 4; j++)
                #pragma unroll
                for (int e = 0; e < 2; e++) {
                    int col = wn + j * 8 + tig * 2 + e;
                    int idx = ((wid & 3) * 64 + col) * 2;
                    sred[idx + 0] = colsum[j*2+e];
                    sred[idx + 1] = colsq [j*2+e];
                }
        }
        __syncthreads();
        if (t < 64) {
            float s = 0.f, q2 = 0.f;
            #pragma unroll
            for (int w = 0; w < 4; w++) {
                s  += sred[(w * 64 + t) * 2 + 0];
                q2 += sred[(w * 64 + t) * 2 + 1];
            }
            int hh, chunk;
            if (EPI == 1) { hh = blockIdx.z >> 2; chunk = (blockIdx.z & 3) * 8 + blockIdx.y; }
            else          { hh = blockIdx.z;      chunk = blockIdx.y; }
            size_t p = ((size_t)(hh * NCH + chunk) * VV + (n0 + t)) * 2;
            part[p + 0] = s;
            part[p + 1] = q2;
        }
    }
}

// ---------------- q/k/v projection (bxBase selects subset) -------------------
// bx+bxBase: 0 -> q, 1 -> k, >=2 -> v col-block (bx+bxBase-2).
__global__ void __launch_bounds__(256, 4)
gemm_qkv(const float* __restrict__ net,
         const float* __restrict__ Wq_t, const float* __restrict__ Wk_t,
         const float* __restrict__ Wv_t,
         float* __restrict__ q, float* __restrict__ k, float* __restrict__ v,
         int bxBase)
{
    const int h = blockIdx.z;
    const int bx = blockIdx.x + bxBase;
    const float* A = net + (size_t)h * BS * VV;
    const float* B;
    float* C;
    int N, n0;
    if (bx == 0)      { B = Wq_t + (size_t)h * TT * VV * KDIM; C = q + (size_t)h * BS * KDIM; N = KDIM; n0 = 0; }
    else if (bx == 1) { B = Wk_t + (size_t)h * TT * VV * KDIM; C = k + (size_t)h * BS * KDIM; N = KDIM; n0 = 0; }
    else              { B = Wv_t + (size_t)h * TT * VV * VV;   C = v + (size_t)h * BS * VV;   N = VV;   n0 = (bx - 2) * GBN; }
    const int K = VV;

    extern __shared__ unsigned smem[];
    unsigned* AsH = smem;
    unsigned* AsL = smem + A_TILE;
    unsigned* BsH = smem + 2*A_TILE;
    unsigned* BsL = smem + 2*A_TILE + B_TILE;

    const int t    = threadIdx.x;
    const int lane = t & 31;
    const int wid  = t >> 5;
    const int gid  = lane >> 2;
    const int tig  = lane & 3;
    const int wm   = (wid & 3) * 32;
    const int wn   = (wid >> 2) * 32;
    const int m0 = blockIdx.y * GBM;

    float acc[2][4][4] = {};

    for (int k0 = 0; k0 < K; k0 += GBK) {
        float4 ar[4];
        #pragma unroll
        for (int i = 0; i < 4; i++) {
            int idx = t + i * 256;
            int r = idx >> 3, c4 = (idx & 7) << 2;
            ar[i] = *(const float4*)&A[(size_t)(m0 + r) * K + k0 + c4];
        }
        float4 br[2];
        #pragma unroll
        for (int i = 0; i < 2; i++) {
            int idx = t + i * 256;
            int r = idx >> 4, c4 = (idx & 15) << 2;
            br[i] = *(const float4*)&B[(size_t)(k0 + r) * N + n0 + c4];
        }
        __syncthreads();
        #pragma unroll
        for (int i = 0; i < 4; i++) {
            int idx = t + i * 256;
            int r = idx >> 3, c4 = (idx & 7) << 2;
            unsigned* ph = &AsH[r * ASTR + c4];
            unsigned* pl = &AsL[r * ASTR + c4];
            split_tf32(ar[i].x, ph[0], pl[0]);
            split_tf32(ar[i].y, ph[1], pl[1]);
            split_tf32(ar[i].z, ph[2], pl[2]);
            split_tf32(ar[i].w, ph[3], pl[3]);
        }
        #pragma unroll
        for (int i = 0; i < 2; i++) {
            int idx = t + i * 256;
            int r = idx >> 4, c4 = (idx & 15) << 2;
            int off = r * BSTR_NN + c4;
            unsigned* ph = &BsH[off];
            unsigned* pl = &BsL[off];
            split_tf32(br[i].x, ph[0], pl[0]);
            split_tf32(br[i].y, ph[1], pl[1]);
            split_tf32(br[i].z, ph[2], pl[2]);
            split_tf32(br[i].w, ph[3], pl[3]);
        }
        __syncthreads();

        #pragma unroll
        for (int ks = 0; ks < 4; ks++) {
            const int kk = ks * 8;
            unsigned aH[2][4], aL[2][4];
            #pragma unroll
            for (int i = 0; i < 2; i++) {
                const int mr = wm + i * 16;
                const int o0 = (mr + gid    ) * ASTR + kk + tig;
                const int o1 = (mr + gid + 8) * ASTR + kk + tig;
                aH[i][0] = AsH[o0];     aL[i][0] = AsL[o0];
                aH[i][1] = AsH[o1];     aL[i][1] = AsL[o1];
                aH[i][2] = AsH[o0 + 4]; aL[i][2] = AsL[o0 + 4];
                aH[i][3] = AsH[o1 + 4]; aL[i][3] = AsL[o1 + 4];
            }
            unsigned bH[4][2], bL[4][2];
            #pragma unroll
            for (int j = 0; j < 4; j++) {
                const int nc = wn + j * 8 + gid;
                int o0 = (kk + tig) * BSTR_NN + nc;
                int o1 = o0 + 4 * BSTR_NN;
                bH[j][0] = BsH[o0]; bL[j][0] = BsL[o0];
                bH[j][1] = BsH[o1]; bL[j][1] = BsL[o1];
            }
            #pragma unroll
            for (int i = 0; i < 2; i++)
                #pragma unroll
                for (int j = 0; j < 4; j++) {
                    mma_tf32(acc[i][j], aL[i], bH[j]);
                    mma_tf32(acc[i][j], aH[i], bL[j]);
                    mma_tf32(acc[i][j], aH[i], bH[j]);
                }
        }
        __syncthreads();
    }

    #pragma unroll
    for (int i = 0; i < 2; i++)
        #pragma unroll
        for (int j = 0; j < 4; j++) {
            const int r0 = m0 + wm + i * 16 + gid;
            const int c0 = n0 + wn + j * 8 + tig * 2;
            *(float2*)&C[(size_t)r0 * N + c0] =
                make_float2(acc[i][j][0], acc[i][j][1]);
            *(float2*)&C[(size_t)(r0 + 8) * N + c0] =
                make_float2(acc[i][j][2], acc[i][j][3]);
        }
}

// ---------------- softmax: one warp per row, shuffle-only reductions ---------
__global__ void __launch_bounds__(128)
softmax_rows(float* __restrict__ s)
{
    const int warp = blockIdx.x * 4 + (threadIdx.x >> 5);
    const int lane = threadIdx.x & 31;
    float4* row = (float4*)(s + (size_t)warp * SS);

    float4 v[8];
    float m = -1e30f;
    #pragma unroll
    for (int i = 0; i < 8; i++) {
        v[i] = row[i * 32 + lane];
        m = fmaxf(m, fmaxf(fmaxf(v[i].x, v[i].y), fmaxf(v[i].z, v[i].w)));
    }
    #pragma unroll
    for (int msk = 16; msk >= 1; msk >>= 1)
        m = fmaxf(m, __shfl_xor_sync(0xffffffffu, m, msk));

    float sum = 0.f;
    #pragma unroll
    for (int i = 0; i < 8; i++) {
        v[i].x = __expf(v[i].x - m);
        v[i].y = __expf(v[i].y - m);
        v[i].z = __expf(v[i].z - m);
        v[i].w = __expf(v[i].w - m);
        sum += (v[i].x + v[i].y) + (v[i].z + v[i].w);
    }
    #pragma unroll
    for (int msk = 16; msk >= 1; msk >>= 1)
        sum += __shfl_xor_sync(0xffffffffu, sum, msk);

    const float inv = 1.f / sum;
    #pragma unroll
    for (int i = 0; i < 8; i++) {
        v[i].x *= inv; v[i].y *= inv; v[i].z *= inv; v[i].w *= inv;
        row[i * 32 + lane] = v[i];
    }
}

// ---------------- batchnorm normalize: dst = norm(src), float4 streamed ------
__global__ void __launch_bounds__(256)
bn_norm(const float* __restrict__ src, float* __restrict__ dst,
        const float* __restrict__ part,
        const float* __restrict__ gamma, const float* __restrict__ beta,
        int gstride)
{
    __shared__ float scS[VV], shS[VV];
    const int t = threadIdx.x;
    const int h = blockIdx.y;
    {
        const float* p = part + (size_t)h * NCH * VV * 2;
        float sum = 0.f, sq = 0.f;
        #pragma unroll
        for (int j = 0; j < NCH; j++) {
            sum += p[((size_t)j*VV + t)*2 + 0];
            sq  += p[((size_t)j*VV + t)*2 + 1];
        }
        const float mean = sum * (1.f / BS);
        const float var  = sq  * (1.f / BS) - mean * mean;
        const float inv  = rsqrtf(var + EPS);
        const float g = gamma[(size_t)h * gstride + t];
        const float b = beta [(size_t)h * gstride + t];
        const float sc = inv * g;
        scS[t] = sc;
        shS[t] = b - mean * sc;
    }
    __syncthreads();

    const float4* s4 = (const float4*)(src + (size_t)h * BS * VV);
    float4*       d4 = (float4*)      (dst + (size_t)h * BS * VV);
    const int total = BS * VV / 4;               // 262144
    const int stride = gridDim.x * 256;
    for (int idx = blockIdx.x * 256 + t; idx < total; idx += stride) {
        const int c4 = (idx & 63) << 2;          // 64 float4 per row
        float4 val = s4[idx];
        val.x = fmaf(val.x, scS[c4+0], shS[c4+0]);
        val.y = fmaf(val.y, scS[c4+1], shS[c4+1]);
        val.z = fmaf(val.z, scS[c4+2], shS[c4+2]);
        val.w = fmaf(val.w, scS[c4+3], shS[c4+3]);
        d4[idx] = val;
    }
}

// ---------------- [H][B*S][V] -> [B,S,H,V], float4 ---------------------------
__global__ void __launch_bounds__(256)
write_out(const float* __restrict__ net, float* __restrict__ out)
{
    const int h = blockIdx.y;
    const int row = blockIdx.x * 4 + (threadIdx.x >> 6);
    const int c4 = threadIdx.x & 63;
    const float4* n4 = (const float4*)(net + (size_t)h * BS * VV);
    float4* o4 = (float4*)out;
    o4[((size_t)row * HH + h) * 64 + c4] = n4[(size_t)row * 64 + c4];
}

// ---------------- launcher ---------------------------------------------------
extern "C" void kernel_launch(void* const* d_in, const int* in_sizes, int n_in,
                              void* d_out, int out_size)
{
    const float* x     = (const float*)d_in[0];
    const float* W_in  = (const float*)d_in[1];
    const float* Wq    = (const float*)d_in[2];
    const float* Wk    = (const float*)d_in[3];
    const float* Wv    = (const float*)d_in[4];
    const float* Wd    = (const float*)d_in[5];
    const float* g1    = (const float*)d_in[6];
    const float* b1    = (const float*)d_in[7];
    const float* g2    = (const float*)d_in[8];
    const float* b2    = (const float*)d_in[9];
    float* out = (float*)d_out;

    float *net, *q, *k, *v, *scores, *z, *part;
    cudaGetSymbolAddress((void**)&net,    g_net);
    cudaGetSymbolAddress((void**)&q,      g_q);
    cudaGetSymbolAddress((void**)&k,      g_k);
    cudaGetSymbolAddress((void**)&v,      g_v);
    cudaGetSymbolAddress((void**)&scores, g_scores);
    cudaGetSymbolAddress((void**)&z,      g_z);
    cudaGetSymbolAddress((void**)&part,   g_part);

    const int smem_bytes = SMEM_U32 * 4;   // 55296
    static int configured = 0;
    static cudaStream_t s1;
    static cudaEvent_t evF[TT], evJ[TT];
    if (!configured) {
        cudaFuncSetAttribute(gemm_mma<0,0>, cudaFuncAttributeMaxDynamicSharedMemorySize, smem_bytes);
        cudaFuncSetAttribute(gemm_mma<1,0>, cudaFuncAttributeMaxDynamicSharedMemorySize, smem_bytes);
        cudaFuncSetAttribute(gemm_mma<0,1>, cudaFuncAttributeMaxDynamicSharedMemorySize, smem_bytes);
        cudaFuncSetAttribute(gemm_mma<0,2>, cudaFuncAttributeMaxDynamicSharedMemorySize, smem_bytes);
        cudaFuncSetAttribute(gemm_qkv,      cudaFuncAttributeMaxDynamicSharedMemorySize, smem_bytes);
        cudaStreamCreateWithFlags(&s1, cudaStreamNonBlocking);
        for (int i = 0; i < TT; i++) {
            cudaEventCreateWithFlags(&evF[i], cudaEventDisableTiming);
            cudaEventCreateWithFlags(&evJ[i], cudaEventDisableTiming);
        }
        configured = 1;
    }

    const cudaStream_t s0 = 0;
    const float scale = 0.125f;   // KD^-0.5

    // net[h] = x @ W_in, replicated to all 8 heads
    gemm_mma<0,0><<<dim3(VV/GBN, BS/GBM, 1), 256, smem_bytes, s0>>>(
        x, W_in, net, nullptr, nullptr, BS, VV, DIN,
        0, 0, 0, 0, 1.f, HH, (long long)BS*VV);

    for (int t = 0; t < TT; t++) {
        // fork: side stream computes q,k -> scores -> softmax
        cudaEventRecord(evF[t], s0);
        cudaStreamWaitEvent(s1, evF[t], 0);

        // q, k on s1 (grid.x = 2: bx 0,1)
        gemm_qkv<<<dim3(2, BS/GBM, HH), 256, smem_bytes, s1>>>(
            net, Wq + (size_t)t*VV*KDIM, Wk + (size_t)t*VV*KDIM,
            Wv + (size_t)t*VV*VV, q, k, v, 0);

        // scores = scale * q @ k^T on s1
        gemm_mma<1,0><<<dim3(SS/GBN, SS/GBM, HH*BB), 256, smem_bytes, s1>>>(
            q, k, scores, nullptr, nullptr, SS, SS, KDIM,
            (long long)SS*KDIM, (long long)SS*KDIM, (long long)SS*SS, 0,
            scale, 1, 0);

        // softmax on s1
        softmax_rows<<<HH*BB*SS/4, 128, 0, s1>>>(scores);
        cudaEventRecord(evJ[t], s1);

        // v on s0 (grid.x = 4: bx 2..5), concurrent with s1 chain
        gemm_qkv<<<dim3(4, BS/GBM, HH), 256, smem_bytes, s0>>>(
            net, Wq + (size_t)t*VV*KDIM, Wk + (size_t)t*VV*KDIM,
            Wv + (size_t)t*VV*VV, q, k, v, 2);

        // join: attnout needs softmax(scores) from s1
        cudaStreamWaitEvent(s0, evJ[t], 0);

        // net = net + scores @ v (in-place residual) + BN partial stats
        gemm_mma<0,1><<<dim3(VV/GBN, SS/GBM, HH*BB), 256, smem_bytes, s0>>>(
            scores, v, net, net, part, SS, VV, SS,
            (long long)SS*SS, (long long)SS*VV, (long long)SS*VV, (long long)SS*VV,
            1.f, 1, 0);
        bn_norm<<<dim3(32, HH), 256, 0, s0>>>(net, net, part,
            g1 + (size_t)t*VV, b1 + (size_t)t*VV, TT*VV);

        // z = net + relu(net @ Wd) + BN partial stats; net = BN(z)
        gemm_mma<0,2><<<dim3(VV/GBN, BS/GBM, HH), 256, smem_bytes, s0>>>(
            net, Wd + (size_t)t*VV*VV, z, net, part, BS, VV, VV,
            (long long)BS*VV, (long long)TT*VV*VV, (long long)BS*VV, (long long)BS*VV,
            1.f, 1, 0);
        bn_norm<<<dim3(32, HH), 256, 0, s0>>>(z, net, part,
            g2 + (size_t)t*VV, b2 + (size_t)t*VV, TT*VV);
    }

    write_out<<<dim3(BS/4, HH), 256, 0, s0>>>(net, out);
}